// round 3
// baseline (speedup 1.0000x reference)
#include <cuda_runtime.h>
#include <cstdint>

#define EXPERTS 16
#define FDIM 128
#define HDIM 256
#define ODIM 64
#define BMAX 262144
#define MMAX (BMAX/EXPERTS)
#define EQCAP 8192

#define BM 128
#define HC 64
#define SXT_STRIDE (BM+4)   // 132
#define SWT_STRIDE (HC+4)   // 68

// ---------------- scratch (no allocations allowed) ----------------
__device__ unsigned g_keys[(size_t)EXPERTS * BMAX];      // 16.8 MB
__device__ unsigned g_hist[EXPERTS * 65536];             // 4 MB
__device__ unsigned g_hist2[EXPERTS * 65536];            // 4 MB
__device__ unsigned g_b16[EXPERTS];
__device__ unsigned g_rankInB[EXPERTS];
__device__ unsigned g_T[EXPERTS];
__device__ unsigned g_needEq[EXPERTS];
__device__ int      g_eqList[EXPERTS * EQCAP];
__device__ int      g_eqCnt[EXPERTS];
__device__ unsigned g_selMask[BMAX];
__device__ int      g_idx[EXPERTS * MMAX];
__device__ int      g_idxCnt[EXPERTS];
__device__ float    g_invm[BMAX];

// ---------------- K1: gate scores -> orderable keys + 16-bit histogram ----------------
__global__ void k_scores(const float* __restrict__ feat, const float* __restrict__ Wg,
                         const float* __restrict__ bg, int B)
{
    __shared__ float sW[EXPERTS*FDIM];
    __shared__ float sb[EXPERTS];
    for (int i = threadIdx.x; i < EXPERTS*FDIM; i += blockDim.x) sW[i] = Wg[i];
    if (threadIdx.x < EXPERTS) sb[threadIdx.x] = bg[threadIdx.x];
    __syncthreads();
    int b = blockIdx.x*blockDim.x + threadIdx.x;
    if (b >= B) return;
    const float4* row = reinterpret_cast<const float4*>(feat + (size_t)b*FDIM);
    float acc[EXPERTS];
#pragma unroll
    for (int e=0;e<EXPERTS;e++) acc[e] = sb[e];
#pragma unroll 4
    for (int j=0;j<FDIM/4;j++){
        float4 x = row[j];
#pragma unroll
        for (int e=0;e<EXPERTS;e++){
            float4 w = *reinterpret_cast<const float4*>(&sW[e*FDIM + j*4]);
            acc[e] += x.x*w.x + x.y*w.y + x.z*w.z + x.w*w.w;
        }
    }
#pragma unroll
    for (int e=0;e<EXPERTS;e++){
        unsigned u = __float_as_uint(acc[e]);
        u = (u & 0x80000000u) ? ~u : (u | 0x80000000u);   // order-preserving key
        g_keys[(size_t)e*B + b] = u;
        atomicAdd(&g_hist[e*65536 + (u>>16)], 1u);
    }
}

// ---------------- K2: per expert, find top-16-bit bucket containing the M-th key ----------------
__global__ void k_findbucket(int Mv)
{
    int e = blockIdx.x;
    const unsigned* h = g_hist + e*65536;
    __shared__ unsigned psum[257];
    int c = threadIdx.x;            // 256 threads, chunk c covers bins descending
    int base = 65535 - c*256;
    unsigned s = 0;
    for (int i=0;i<256;i++) s += h[base - i];
    psum[c] = s;
    __syncthreads();
    if (c == 0){
        unsigned acc = 0;
        for (int k=0;k<256;k++){ unsigned t = psum[k]; psum[k] = acc; acc += t; }
        psum[256] = acc;
    }
    __syncthreads();
    unsigned before = psum[c], after = psum[c+1];
    if (before < (unsigned)Mv && (unsigned)Mv <= after){
        unsigned acc = before;
        for (int i=0;i<256;i++){
            unsigned cnt = h[base - i];
            if (acc + cnt >= (unsigned)Mv){
                g_b16[e]    = (unsigned)(base - i);
                g_rankInB[e]= (unsigned)Mv - acc;   // rank needed inside bucket (1-based)
                break;
            }
            acc += cnt;
        }
    }
}

// ---------------- K3: low-16-bit histogram restricted to critical bucket ----------------
__global__ void k_hist2(int B){
    int e = blockIdx.y;
    int i = blockIdx.x*blockDim.x + threadIdx.x;
    if (i >= B) return;
    unsigned u = g_keys[(size_t)e*B + i];
    if ((u >> 16) == g_b16[e]) atomicAdd(&g_hist2[e*65536 + (u & 0xFFFFu)], 1u);
}

// ---------------- K4: exact threshold key T + number of equal keys needed ----------------
__global__ void k_findthresh()
{
    int e = blockIdx.x;
    const unsigned* h = g_hist2 + e*65536;
    unsigned target = g_rankInB[e];
    __shared__ unsigned psum[257];
    int c = threadIdx.x;
    int base = 65535 - c*256;
    unsigned s=0;
    for (int i=0;i<256;i++) s += h[base - i];
    psum[c]=s; __syncthreads();
    if (c==0){ unsigned acc=0; for(int k=0;k<256;k++){unsigned t=psum[k];psum[k]=acc;acc+=t;} psum[256]=acc; }
    __syncthreads();
    unsigned before=psum[c], after=psum[c+1];
    if (before < target && target <= after){
        unsigned acc=before;
        for (int i=0;i<256;i++){
            unsigned cnt = h[base-i];
            if (acc + cnt >= target){
                g_T[e]      = (g_b16[e]<<16) | (unsigned)(base-i);
                g_needEq[e] = target - acc;      // ties to take, smallest-index first
                break;
            }
            acc += cnt;
        }
    }
}

// ---------------- K5: select key > T; collect key == T candidates ----------------
__global__ void k_select(int B){
    int e = blockIdx.y;
    int i = blockIdx.x*blockDim.x + threadIdx.x;
    if (i >= B) return;
    unsigned u = g_keys[(size_t)e*B + i];
    unsigned t = g_T[e];
    if (u > t){
        int p = atomicAdd(&g_idxCnt[e], 1);
        g_idx[e*MMAX + p] = i;
        atomicOr(&g_selMask[i], 1u << e);
    } else if (u == t){
        int p = atomicAdd(&g_eqCnt[e], 1);
        if (p < EQCAP) g_eqList[e*EQCAP + p] = i;
    }
}

// ---------------- K6: resolve ties by smallest index (matches jax.lax.top_k) ----------------
__global__ void k_resolve()
{
    int e = blockIdx.x;
    int n = g_eqCnt[e]; if (n > EQCAP) n = EQCAP;
    int need = (int)g_needEq[e];
    for (int j = threadIdx.x; j < n; j += blockDim.x){
        int v = g_eqList[e*EQCAP + j];
        int r = 0;
        for (int k=0;k<n;k++) r += (g_eqList[e*EQCAP + k] < v);
        if (r < need){
            int p = atomicAdd(&g_idxCnt[e], 1);
            g_idx[e*MMAX + p] = v;
            atomicOr(&g_selMask[v], 1u << e);
        }
    }
}

// ---------------- K7: 1/m per token ----------------
__global__ void k_invm(int B){
    int i = blockIdx.x*blockDim.x + threadIdx.x;
    if (i>=B) return;
    int c = __popc(g_selMask[i]);
    g_invm[i] = 1.0f / (float)(c > 0 ? c : 1);
}

// ---------------- K8: fused gather -> (X W1^T + b1).relu -> (H W2^T + b2) -> scatter-add ----------------
__global__ __launch_bounds__(256, 1)
void k_mlp(const float* __restrict__ feat,
           const float* __restrict__ W1, const float* __restrict__ b1,
           const float* __restrict__ W2, const float* __restrict__ b2,
           float* __restrict__ out, int Mv)
{
    extern __shared__ float smbuf[];
    float* sXT  = smbuf;                        // [FDIM][BM+4]  (f-major, m-contig)
    float* sWT  = sXT + FDIM*SXT_STRIDE;        // [FDIM][HC+4]
    float* sHT  = sWT + FDIM*SWT_STRIDE;        // [HC][BM+4]
    float* sW2T = sHT + HC*SXT_STRIDE;          // [HC][ODIM+4] (ODIM==HC)
    float* sB1  = sW2T + HC*SWT_STRIDE;         // [HC]
    float* sB2  = sB1 + HC;                     // [ODIM]
    float* sInvm= sB2 + ODIM;                   // [BM]
    int*   sIdx = (int*)(sInvm + BM);           // [BM]

    int e    = blockIdx.y;
    int tile = blockIdx.x;
    int tid  = threadIdx.x;
    int slot0 = tile*BM;

    if (tid < BM){
        int s = slot0 + tid;
        int t = (s < Mv) ? g_idx[e*MMAX + s] : 0;
        sIdx[tid]  = t;
        sInvm[tid] = (s < Mv) ? g_invm[t] : 0.0f;   // w=0 -> padded slot contributes nothing
    }
    if (tid < ODIM) sB2[tid] = b2[e*ODIM + tid];
    __syncthreads();

    // gather X transposed: lanes map to m (contig) so STS is conflict-free
#pragma unroll
    for (int it=0; it<16; ++it){
        int lin = it*256 + tid;
        int m = lin & (BM-1);
        int q = lin >> 7;                     // 0..31
        float4 v = *reinterpret_cast<const float4*>(feat + (size_t)sIdx[m]*FDIM + q*4);
        sXT[(q*4+0)*SXT_STRIDE + m] = v.x;
        sXT[(q*4+1)*SXT_STRIDE + m] = v.y;
        sXT[(q*4+2)*SXT_STRIDE + m] = v.z;
        sXT[(q*4+3)*SXT_STRIDE + m] = v.w;
    }

    int tm = tid >> 4;     // 0..15 -> m block
    int th = tid & 15;     // 0..15 -> h/o block
    int m0 = tm*8;
    int h0 = th*4;
    int o0 = th*4;

    float acc2[8][4];
#pragma unroll
    for (int i=0;i<8;i++)
#pragma unroll
        for (int j=0;j<4;j++) acc2[i][j]=0.0f;

    for (int c=0;c<HDIM/HC;c++){
        // W1 chunk transposed (lanes -> h contig, conflict-free STS)
#pragma unroll
        for (int it=0; it<8; ++it){
            int lin = it*256 + tid;
            int hh = lin & 63;
            int q  = lin >> 6;                // 0..31
            float4 v = *reinterpret_cast<const float4*>(W1 + ((size_t)e*HDIM + c*HC + hh)*FDIM + q*4);
            sWT[(q*4+0)*SWT_STRIDE + hh] = v.x;
            sWT[(q*4+1)*SWT_STRIDE + hh] = v.y;
            sWT[(q*4+2)*SWT_STRIDE + hh] = v.z;
            sWT[(q*4+3)*SWT_STRIDE + hh] = v.w;
        }
        // W2 chunk transposed (lanes -> o contig)
#pragma unroll
        for (int it=0; it<4; ++it){
            int lin = it*256 + tid;
            int oo = lin & 63;
            int hq = lin >> 6;                // 0..15
            float4 v = *reinterpret_cast<const float4*>(W2 + ((size_t)e*ODIM + oo)*HDIM + c*HC + hq*4);
            sW2T[(hq*4+0)*SWT_STRIDE + oo] = v.x;
            sW2T[(hq*4+1)*SWT_STRIDE + oo] = v.y;
            sW2T[(hq*4+2)*SWT_STRIDE + oo] = v.z;
            sW2T[(hq*4+3)*SWT_STRIDE + oo] = v.w;
        }
        if (tid < HC) sB1[tid] = b1[e*HDIM + c*HC + tid];
        __syncthreads();

        // GEMM1: H[m][h] = sum_f X[m][f] W1[h][f]
        float acc1[4][8];
#pragma unroll
        for (int j=0;j<4;j++)
#pragma unroll
            for (int i=0;i<8;i++) acc1[j][i]=0.0f;

#pragma unroll 4
        for (int f=0; f<FDIM; ++f){
            const float* ax = &sXT[f*SXT_STRIDE + m0];
            float4 a0 = *reinterpret_cast<const float4*>(ax);
            float4 a1 = *reinterpret_cast<const float4*>(ax+4);
            float4 bv = *reinterpret_cast<const float4*>(&sWT[f*SWT_STRIDE + h0]);
            float a[8] = {a0.x,a0.y,a0.z,a0.w,a1.x,a1.y,a1.z,a1.w};
            float bb[4] = {bv.x,bv.y,bv.z,bv.w};
#pragma unroll
            for (int j=0;j<4;j++)
#pragma unroll
                for (int i=0;i<8;i++)
                    acc1[j][i] += a[i]*bb[j];
        }

        // relu + bias, store H transposed (vectorized STS)
#pragma unroll
        for (int j=0;j<4;j++){
            float bias = sB1[h0+j];
            float4 v0, v1;
            v0.x = fmaxf(acc1[j][0]+bias, 0.0f);
            v0.y = fmaxf(acc1[j][1]+bias, 0.0f);
            v0.z = fmaxf(acc1[j][2]+bias, 0.0f);
            v0.w = fmaxf(acc1[j][3]+bias, 0.0f);
            v1.x = fmaxf(acc1[j][4]+bias, 0.0f);
            v1.y = fmaxf(acc1[j][5]+bias, 0.0f);
            v1.z = fmaxf(acc1[j][6]+bias, 0.0f);
            v1.w = fmaxf(acc1[j][7]+bias, 0.0f);
            *reinterpret_cast<float4*>(&sHT[(h0+j)*SXT_STRIDE + m0])     = v0;
            *reinterpret_cast<float4*>(&sHT[(h0+j)*SXT_STRIDE + m0 + 4]) = v1;
        }
        __syncthreads();

        // GEMM2: Y[m][o] += sum_h H[m][h] W2[o][h]
#pragma unroll 4
        for (int h=0; h<HC; ++h){
            const float* ax = &sHT[h*SXT_STRIDE + m0];
            float4 a0 = *reinterpret_cast<const float4*>(ax);
            float4 a1 = *reinterpret_cast<const float4*>(ax+4);
            float4 bv = *reinterpret_cast<const float4*>(&sW2T[h*SWT_STRIDE + o0]);
            float a[8]={a0.x,a0.y,a0.z,a0.w,a1.x,a1.y,a1.z,a1.w};
            float bb[4]={bv.x,bv.y,bv.z,bv.w};
#pragma unroll
            for (int j=0;j<4;j++)
#pragma unroll
                for (int i=0;i<8;i++)
                    acc2[i][j] += a[i]*bb[j];
        }
        __syncthreads();   // protect sWT/sW2T/sHT before next chunk's loads
    }

    // scatter-add combine with 1/m weight (bias b2 added per (e,m) pair before weighting)
#pragma unroll
    for (int i=0;i<8;i++){
        int m = m0+i;
        int t = sIdx[m];
        float w = sInvm[m];
#pragma unroll
        for (int j=0;j<4;j++){
            atomicAdd(&out[(size_t)t*ODIM + o0 + j], (acc2[i][j] + sB2[o0+j]) * w);
        }
    }
}

// ---------------- launch ----------------
extern "C" void kernel_launch(void* const* d_in, const int* in_sizes, int n_in,
                              void* d_out, int out_size)
{
    const float* feat = (const float*)d_in[0];
    const float* Wg   = (const float*)d_in[1];
    const float* bg   = (const float*)d_in[2];
    const float* W1   = (const float*)d_in[3];
    const float* b1   = (const float*)d_in[4];
    const float* W2   = (const float*)d_in[5];
    const float* b2   = (const float*)d_in[6];
    float* out = (float*)d_out;

    int B = in_sizes[0] / FDIM;
    int Mv = (B + EXPERTS - 1) / EXPERTS;   // ceil(capacity_factor * B / E), cf=1.0
    if (Mv < 1) Mv = 1;
    if (Mv > B) Mv = B;

    void *p_hist, *p_hist2, *p_selMask, *p_eqCnt, *p_idxCnt;
    cudaGetSymbolAddress(&p_hist,    g_hist);
    cudaGetSymbolAddress(&p_hist2,   g_hist2);
    cudaGetSymbolAddress(&p_selMask, g_selMask);
    cudaGetSymbolAddress(&p_eqCnt,   g_eqCnt);
    cudaGetSymbolAddress(&p_idxCnt,  g_idxCnt);

    cudaMemsetAsync(p_hist,    0, (size_t)EXPERTS*65536*sizeof(unsigned), 0);
    cudaMemsetAsync(p_hist2,   0, (size_t)EXPERTS*65536*sizeof(unsigned), 0);
    cudaMemsetAsync(p_selMask, 0, (size_t)B*sizeof(unsigned), 0);
    cudaMemsetAsync(p_eqCnt,   0, (size_t)EXPERTS*sizeof(int), 0);
    cudaMemsetAsync(p_idxCnt,  0, (size_t)EXPERTS*sizeof(int), 0);
    cudaMemsetAsync(d_out,     0, (size_t)out_size*sizeof(float), 0);

    int tb = 256;
    int gb = (B + tb - 1)/tb;
    k_scores<<<gb, tb>>>(feat, Wg, bg, B);
    k_findbucket<<<EXPERTS, 256>>>(Mv);
    k_hist2<<<dim3(gb, EXPERTS), tb>>>(B);
    k_findthresh<<<EXPERTS, 256>>>();
    k_select<<<dim3(gb, EXPERTS), tb>>>(B);
    k_resolve<<<EXPERTS, 256>>>();
    k_invm<<<gb, tb>>>(B);

    size_t shmem = (size_t)(FDIM*SXT_STRIDE + FDIM*SWT_STRIDE + HC*SXT_STRIDE
                            + HC*SWT_STRIDE + HC + ODIM + BM) * sizeof(float)
                 + (size_t)BM * sizeof(int);
    cudaFuncSetAttribute(k_mlp, cudaFuncAttributeMaxDynamicSharedMemorySize, (int)shmem);
    int mtiles = (Mv + BM - 1)/BM;
    k_mlp<<<dim3(mtiles, EXPERTS), 256, shmem>>>(feat, W1, b1, W2, b2, out, Mv);
}

// round 6
// speedup vs baseline: 1.7311x; 1.7311x over previous
#include <cuda_runtime.h>
#include <cuda_bf16.h>
#include <cstdint>

#define EXPERTS 16
#define FDIM 128
#define HDIM 256
#define ODIM 64
#define BMAX 262144
#define MMAX (BMAX/EXPERTS)
#define EQCAP 8192
#define BM 128

// ---------------- scratch ----------------
__device__ unsigned g_keys[(size_t)EXPERTS * BMAX];
__device__ unsigned g_hist[EXPERTS * 65536];
__device__ unsigned g_hist2[EXPERTS * 65536];
__device__ unsigned g_b16[EXPERTS];
__device__ unsigned g_rankInB[EXPERTS];
__device__ unsigned g_T[EXPERTS];
__device__ unsigned g_needEq[EXPERTS];
__device__ int      g_eqList[EXPERTS * EQCAP];
__device__ int      g_eqCnt[EXPERTS];
__device__ unsigned g_selMask[BMAX];
__device__ int      g_idx[EXPERTS * MMAX];
__device__ int      g_idxCnt[EXPERTS];
__device__ float    g_invm[BMAX];

// ---------------- helpers ----------------
__device__ __forceinline__ uint32_t smem_u32(const void* p) {
    uint32_t a;
    asm("{ .reg .u64 t; cvta.to.shared.u64 t, %1; cvt.u32.u64 %0, t; }" : "=r"(a) : "l"(p));
    return a;
}
#define LDSM_X4(r0,r1,r2,r3, addr) \
    asm volatile("ldmatrix.sync.aligned.m8n8.x4.shared.b16 {%0,%1,%2,%3}, [%4];" \
        : "=r"(r0),"=r"(r1),"=r"(r2),"=r"(r3) : "r"(addr))
#define MMA16816(d, a, b) \
    asm volatile("mma.sync.aligned.m16n8k16.row.col.f32.bf16.bf16.f32 " \
        "{%0,%1,%2,%3}, {%4,%5,%6,%7}, {%8,%9}, {%0,%1,%2,%3};" \
        : "+f"((d)[0]),"+f"((d)[1]),"+f"((d)[2]),"+f"((d)[3]) \
        : "r"((a)[0]),"r"((a)[1]),"r"((a)[2]),"r"((a)[3]), "r"((b)[0]),"r"((b)[1]))

__device__ __forceinline__ void split2(float x0, float x1, unsigned &hw, unsigned &lw) {
    __nv_bfloat16 h0 = __float2bfloat16(x0), h1 = __float2bfloat16(x1);
    float r0 = x0 - __bfloat162float(h0), r1 = x1 - __bfloat162float(h1);
    __nv_bfloat16 l0 = __float2bfloat16(r0), l1 = __float2bfloat16(r1);
    hw = (unsigned)__bfloat16_as_ushort(h0) | ((unsigned)__bfloat16_as_ushort(h1) << 16);
    lw = (unsigned)__bfloat16_as_ushort(l0) | ((unsigned)__bfloat16_as_ushort(l1) << 16);
}
__device__ __forceinline__ void split8(const float* x, uint4& vh, uint4& vl) {
    unsigned h0,h1,h2,h3,l0,l1,l2,l3;
    split2(x[0],x[1],h0,l0); split2(x[2],x[3],h1,l1);
    split2(x[4],x[5],h2,l2); split2(x[6],x[7],h3,l3);
    vh = make_uint4(h0,h1,h2,h3); vl = make_uint4(l0,l1,l2,l3);
}
// XOR swizzle: 16B chunk index xored with (row&7); 256B rows
__device__ __forceinline__ unsigned swz(int row, int chunk) {
    return (unsigned)(row*256 + ((chunk ^ (row&7)) << 4));
}

// ---------------- K1: gate scores (exact fp32) ----------------
__global__ void k_scores(const float* __restrict__ feat, const float* __restrict__ Wg,
                         const float* __restrict__ bg, int B)
{
    __shared__ float sW[EXPERTS*FDIM];
    __shared__ float sb[EXPERTS];
    for (int i = threadIdx.x; i < EXPERTS*FDIM; i += blockDim.x) sW[i] = Wg[i];
    if (threadIdx.x < EXPERTS) sb[threadIdx.x] = bg[threadIdx.x];
    __syncthreads();
    int b = blockIdx.x*blockDim.x + threadIdx.x;
    if (b >= B) return;
    const float4* row = reinterpret_cast<const float4*>(feat + (size_t)b*FDIM);
    float acc[EXPERTS];
#pragma unroll
    for (int e=0;e<EXPERTS;e++) acc[e] = sb[e];
#pragma unroll 4
    for (int j=0;j<FDIM/4;j++){
        float4 x = row[j];
#pragma unroll
        for (int e=0;e<EXPERTS;e++){
            float4 w = *reinterpret_cast<const float4*>(&sW[e*FDIM + j*4]);
            acc[e] += x.x*w.x + x.y*w.y + x.z*w.z + x.w*w.w;
        }
    }
#pragma unroll
    for (int e=0;e<EXPERTS;e++){
        unsigned u = __float_as_uint(acc[e]);
        u = (u & 0x80000000u) ? ~u : (u | 0x80000000u);
        g_keys[(size_t)e*B + b] = u;
        atomicAdd(&g_hist[e*65536 + (u>>16)], 1u);
    }
}

// ---------------- descending scan over 65536 bins ----------------
__device__ __forceinline__ void scan_find(const unsigned* __restrict__ hist, unsigned target,
                                          unsigned* out_bin, unsigned* out_rank)
{
    int t = threadIdx.x;
    const uint4* h4 = reinterpret_cast<const uint4*>(hist);
    int base4 = 16384 - 16*(t+1);
    unsigned s = 0;
#pragma unroll
    for (int i=0;i<16;i++){ uint4 v = h4[base4+i]; s += v.x+v.y+v.z+v.w; }
    __shared__ unsigned warpSum[32], warpPre[32];
    unsigned lane = t & 31, wid = t >> 5;
    unsigned inc = s;
#pragma unroll
    for (int o=1;o<32;o<<=1){ unsigned n = __shfl_up_sync(~0u, inc, o); if (lane >= o) inc += n; }
    if (lane == 31) warpSum[wid] = inc;
    __syncthreads();
    if (wid == 0){
        unsigned ws = warpSum[lane], winc = ws;
#pragma unroll
        for (int o=1;o<32;o<<=1){ unsigned n = __shfl_up_sync(~0u, winc, o); if (lane >= o) winc += n; }
        warpPre[lane] = winc - ws;
    }
    __syncthreads();
    unsigned before = warpPre[wid] + inc - s;
    unsigned after  = before + s;
    if (before < target && target <= after){
        unsigned acc = before;
        int hi = 65535 - 64*t;
        for (int b = hi; b > hi-64; --b){
            unsigned cnt = hist[b];
            if (acc + cnt >= target){ *out_bin = (unsigned)b; *out_rank = target - acc; break; }
            acc += cnt;
        }
    }
}

__global__ void k_findbucket(int Mv){
    int e = blockIdx.x;
    scan_find(g_hist + e*65536, (unsigned)Mv, &g_b16[e], &g_rankInB[e]);
}
__global__ void k_findthresh2(){
    int e = blockIdx.x;
    __shared__ unsigned sBin, sRank;
    if (threadIdx.x == 0){ sBin = 0xFFFFFFFFu; sRank = 0; }
    __syncthreads();
    scan_find(g_hist2 + e*65536, g_rankInB[e], &sBin, &sRank);
    __syncthreads();
    if (threadIdx.x == 0){
        g_T[e] = (g_b16[e] << 16) | sBin;
        g_needEq[e] = sRank;
    }
}

__global__ void k_hist2(int B){
    int e = blockIdx.y;
    int i = blockIdx.x*blockDim.x + threadIdx.x;
    if (i >= B) return;
    unsigned u = g_keys[(size_t)e*B + i];
    if ((u >> 16) == g_b16[e]) atomicAdd(&g_hist2[e*65536 + (u & 0xFFFFu)], 1u);
}

__global__ void k_select(int B){
    int e = blockIdx.y;
    int i = blockIdx.x*blockDim.x + threadIdx.x;
    if (i >= B) return;
    unsigned u = g_keys[(size_t)e*B + i];
    unsigned t = g_T[e];
    if (u > t){
        int p = atomicAdd(&g_idxCnt[e], 1);
        g_idx[e*MMAX + p] = i;
        atomicOr(&g_selMask[i], 1u << e);
    } else if (u == t){
        int p = atomicAdd(&g_eqCnt[e], 1);
        if (p < EQCAP) g_eqList[e*EQCAP + p] = i;
    }
}

__global__ void k_resolve(){
    int e = blockIdx.x;
    int n = g_eqCnt[e]; if (n > EQCAP) n = EQCAP;
    int need = (int)g_needEq[e];
    for (int j = threadIdx.x; j < n; j += blockDim.x){
        int v = g_eqList[e*EQCAP + j];
        int r = 0;
        for (int k=0;k<n;k++) r += (g_eqList[e*EQCAP + k] < v);
        if (r < need){
            int p = atomicAdd(&g_idxCnt[e], 1);
            g_idx[e*MMAX + p] = v;
            atomicOr(&g_selMask[v], 1u << e);
        }
    }
}

__global__ void k_invm(int B){
    int i = blockIdx.x*blockDim.x + threadIdx.x;
    if (i>=B) return;
    int c = __popc(g_selMask[i]);
    g_invm[i] = 1.0f / (float)(c > 0 ? c : 1);
}

// ---------------- K8: mma.sync bf16x3 fused MLP ----------------
// header
#define HDR_IDX   0       // 128 ints
#define HDR_INVM  512     // 128 floats
#define HDR_B1    1024    // 256 floats
#define HDR_B2    2048    // 64 floats
#define POOL      2560
// regions (bf16 matrices, 256B rows, swizzled)
#define OFF_XH  (POOL + 0)        // X hi  [128 x 128]  32KB
#define OFF_XL  (POOL + 32768)
#define OFF_W1H (POOL + 65536)    // W1 half hi [128 x 128] 32KB
#define OFF_W1L (POOL + 98304)
#define OFF_HH  (POOL + 131072)   // H half hi [128 x 128] 32KB
#define OFF_HL  (POOL + 163840)
#define OFF_W2H (POOL + 196608)   // W2 half hi [64 x 128] 16KB
#define OFF_W2L (POOL + 212992)
#define SMEM_TOTAL (POOL + 229376)   // 231936 bytes

__global__ __launch_bounds__(256, 1)
void k_mlp(const float* __restrict__ feat,
           const float* __restrict__ W1, const float* __restrict__ b1,
           const float* __restrict__ W2, const float* __restrict__ b2,
           float* __restrict__ out, int Mv)
{
    extern __shared__ char smem[];
    uint32_t sbase = smem_u32(smem);
    int tid = threadIdx.x, lane = tid & 31, wid = tid >> 5;
    int e = blockIdx.y;
    int slot0 = blockIdx.x * BM;

    int*   sIdx  = (int*)(smem + HDR_IDX);
    float* sInvm = (float*)(smem + HDR_INVM);
    float* sB1   = (float*)(smem + HDR_B1);
    float* sB2   = (float*)(smem + HDR_B2);

    if (tid < BM){
        int s = slot0 + tid;
        int t = (s < Mv) ? g_idx[e*MMAX + s] : 0;
        sIdx[tid]  = t;
        sInvm[tid] = (s < Mv) ? g_invm[t] : 0.0f;
    }
    sB1[tid] = b1[e*HDIM + tid];
    if (tid < ODIM) sB2[tid] = b2[e*ODIM + tid];
    __syncthreads();

    // ---- gather X [128 tokens x 128 f], hi/lo split, swizzled ----
#pragma unroll
    for (int it=0; it<8; ++it){
        int s = it*256 + tid;        // 0..2047: (row, chunk)
        int row = s >> 4, cg = s & 15;
        const float* src = feat + (size_t)sIdx[row]*FDIM + cg*8;
        float x[8];
        *(float4*)&x[0] = *(const float4*)(src);
        *(float4*)&x[4] = *(const float4*)(src+4);
        uint4 vh, vl; split8(x, vh, vl);
        unsigned off = swz(row, cg);
        *(uint4*)(smem + OFF_XH + off) = vh;
        *(uint4*)(smem + OFF_XL + off) = vl;
    }

    int wm = wid & 1, wn = wid >> 1;     // 2 x 4 warp grid
    int m0 = wm * 64;

    float c2[4][2][4];
#pragma unroll
    for (int a=0;a<4;a++)
#pragma unroll
        for (int bb=0;bb<2;bb++)
#pragma unroll
            for (int i=0;i<4;i++) c2[a][bb][i] = 0.0f;

    for (int h=0; h<2; ++h){
        __syncthreads();   // previous-iteration readers done before overwrite
        // load W1 half [128 x 128]
#pragma unroll
        for (int it=0; it<8; ++it){
            int s = it*256 + tid;
            int row = s >> 4, cg = s & 15;
            const float* src = W1 + ((size_t)e*HDIM + h*128 + row)*FDIM + cg*8;
            float x[8];
            *(float4*)&x[0] = *(const float4*)(src);
            *(float4*)&x[4] = *(const float4*)(src+4);
            uint4 vh, vl; split8(x, vh, vl);
            unsigned off = swz(row, cg);
            *(uint4*)(smem + OFF_W1H + off) = vh;
            *(uint4*)(smem + OFF_W1L + off) = vl;
        }
        // load W2 half [64 x 128]
#pragma unroll
        for (int it=0; it<4; ++it){
            int s = it*256 + tid;
            int row = s >> 4, cg = s & 15;
            const float* src = W2 + ((size_t)e*ODIM + row)*HDIM + h*128 + cg*8;
            float x[8];
            *(float4*)&x[0] = *(const float4*)(src);
            *(float4*)&x[4] = *(const float4*)(src+4);
            uint4 vh, vl; split8(x, vh, vl);
            unsigned off = swz(row, cg);
            *(uint4*)(smem + OFF_W2H + off) = vh;
            *(uint4*)(smem + OFF_W2L + off) = vl;
        }
        __syncthreads();

        // ---- GEMM1 half: C1[128,128] = X * W1half^T ----
        float c1[4][4][4];
#pragma unroll
        for (int a=0;a<4;a++)
#pragma unroll
            for (int bb=0;bb<4;bb++)
#pragma unroll
                for (int i=0;i<4;i++) c1[a][bb][i] = 0.0f;

#pragma unroll 1
        for (int ks=0; ks<8; ++ks){
            uint32_t ah[4][4], al[4][4];
            int arow_l = lane & 15, achk = ks*2 + (lane >> 4);
#pragma unroll
            for (int mt=0; mt<4; ++mt){
                int row = m0 + mt*16 + arow_l;
                unsigned off = swz(row, achk);
                LDSM_X4(ah[mt][0],ah[mt][1],ah[mt][2],ah[mt][3], sbase + OFF_XH + off);
                LDSM_X4(al[mt][0],al[mt][1],al[mt][2],al[mt][3], sbase + OFF_XL + off);
            }
            uint32_t bh[4][2], bl[4][2];
            int brow_l = (lane & 7) + ((lane >> 4) << 3);
            int bchk = ks*2 + ((lane >> 3) & 1);
#pragma unroll
            for (int np=0; np<2; ++np){
                int nrow = wn*32 + np*16 + brow_l;
                unsigned off = swz(nrow, bchk);
                uint32_t t0,t1,t2,t3;
                LDSM_X4(t0,t1,t2,t3, sbase + OFF_W1H + off);
                bh[np*2][0]=t0; bh[np*2][1]=t1; bh[np*2+1][0]=t2; bh[np*2+1][1]=t3;
                LDSM_X4(t0,t1,t2,t3, sbase + OFF_W1L + off);
                bl[np*2][0]=t0; bl[np*2][1]=t1; bl[np*2+1][0]=t2; bl[np*2+1][1]=t3;
            }
#pragma unroll
            for (int mt=0; mt<4; ++mt)
#pragma unroll
                for (int nf=0; nf<4; ++nf){
                    MMA16816(c1[mt][nf], ah[mt], bh[nf]);
                    MMA16816(c1[mt][nf], ah[mt], bl[nf]);
                    MMA16816(c1[mt][nf], al[mt], bh[nf]);
                }
        }

        // epilogue1: +b1, relu, split -> H half smem
#pragma unroll
        for (int mt=0; mt<4; ++mt)
#pragma unroll
            for (int nf=0; nf<4; ++nf)
#pragma unroll
                for (int i2=0; i2<2; ++i2){
                    int row = m0 + mt*16 + (lane>>2) + 8*i2;
                    int col = wn*32 + nf*8 + (lane&3)*2;
                    float v0 = fmaxf(c1[mt][nf][i2*2+0] + sB1[h*128 + col],     0.0f);
                    float v1 = fmaxf(c1[mt][nf][i2*2+1] + sB1[h*128 + col + 1], 0.0f);
                    unsigned hw, lw; split2(v0, v1, hw, lw);
                    unsigned off = swz(row, col>>3) + (col&7)*2;
                    *(uint32_t*)(smem + OFF_HH + off) = hw;
                    *(uint32_t*)(smem + OFF_HL + off) = lw;
                }
        __syncthreads();

        // ---- GEMM2 partial: C2 += Hhalf * W2half^T ----
#pragma unroll 1
        for (int ks=0; ks<8; ++ks){
            uint32_t ah[4][4], al[4][4];
            int arow_l = lane & 15, achk = ks*2 + (lane >> 4);
#pragma unroll
            for (int mt=0; mt<4; ++mt){
                int row = m0 + mt*16 + arow_l;
                unsigned off = swz(row, achk);
                LDSM_X4(ah[mt][0],ah[mt][1],ah[mt][2],ah[mt][3], sbase + OFF_HH + off);
                LDSM_X4(al[mt][0],al[mt][1],al[mt][2],al[mt][3], sbase + OFF_HL + off);
            }
            uint32_t bh[2][2], bl[2][2];
            {
                int nrow = wn*16 + (lane & 7) + ((lane >> 4) << 3);
                int bchk = ks*2 + ((lane >> 3) & 1);
                unsigned off = swz(nrow, bchk);
                uint32_t t0,t1,t2,t3;
                LDSM_X4(t0,t1,t2,t3, sbase + OFF_W2H + off);
                bh[0][0]=t0; bh[0][1]=t1; bh[1][0]=t2; bh[1][1]=t3;
                LDSM_X4(t0,t1,t2,t3, sbase + OFF_W2L + off);
                bl[0][0]=t0; bl[0][1]=t1; bl[1][0]=t2; bl[1][1]=t3;
            }
#pragma unroll
            for (int mt=0; mt<4; ++mt)
#pragma unroll
                for (int nf=0; nf<2; ++nf){
                    MMA16816(c2[mt][nf], ah[mt], bh[nf]);
                    MMA16816(c2[mt][nf], ah[mt], bl[nf]);
                    MMA16816(c2[mt][nf], al[mt], bh[nf]);
                }
        }
    }

    // ---- final epilogue: +b2, x 1/m, scatter-add ----
#pragma unroll
    for (int mt=0; mt<4; ++mt)
#pragma unroll
        for (int nf=0; nf<2; ++nf)
#pragma unroll
            for (int i=0; i<4; ++i){
                int row = m0 + mt*16 + (lane>>2) + 8*(i>>1);
                int col = wn*16 + nf*8 + (lane&3)*2 + (i&1);
                int tkn = sIdx[row];
                float w = sInvm[row];
                atomicAdd(&out[(size_t)tkn*ODIM + col], (c2[mt][nf][i] + sB2[col]) * w);
            }
}

// ---------------- launch ----------------
extern "C" void kernel_launch(void* const* d_in, const int* in_sizes, int n_in,
                              void* d_out, int out_size)
{
    const float* feat = (const float*)d_in[0];
    const float* Wg   = (const float*)d_in[1];
    const float* bg   = (const float*)d_in[2];
    const float* W1   = (const float*)d_in[3];
    const float* b1   = (const float*)d_in[4];
    const float* W2   = (const float*)d_in[5];
    const float* b2   = (const float*)d_in[6];
    float* out = (float*)d_out;

    int B = in_sizes[0] / FDIM;
    int Mv = (B + EXPERTS - 1) / EXPERTS;
    if (Mv < 1) Mv = 1;
    if (Mv > B) Mv = B;

    void *p_hist, *p_hist2, *p_selMask, *p_eqCnt, *p_idxCnt;
    cudaGetSymbolAddress(&p_hist,    g_hist);
    cudaGetSymbolAddress(&p_hist2,   g_hist2);
    cudaGetSymbolAddress(&p_selMask, g_selMask);
    cudaGetSymbolAddress(&p_eqCnt,   g_eqCnt);
    cudaGetSymbolAddress(&p_idxCnt,  g_idxCnt);

    cudaMemsetAsync(p_hist,    0, (size_t)EXPERTS*65536*sizeof(unsigned), 0);
    cudaMemsetAsync(p_hist2,   0, (size_t)EXPERTS*65536*sizeof(unsigned), 0);
    cudaMemsetAsync(p_selMask, 0, (size_t)B*sizeof(unsigned), 0);
    cudaMemsetAsync(p_eqCnt,   0, (size_t)EXPERTS*sizeof(int), 0);
    cudaMemsetAsync(p_idxCnt,  0, (size_t)EXPERTS*sizeof(int), 0);
    cudaMemsetAsync(d_out,     0, (size_t)out_size*sizeof(float), 0);

    int tb = 256;
    int gb = (B + tb - 1)/tb;
    k_scores<<<gb, tb>>>(feat, Wg, bg, B);
    k_findbucket<<<EXPERTS, 1024>>>(Mv);
    k_hist2<<<dim3(gb, EXPERTS), tb>>>(B);
    k_findthresh2<<<EXPERTS, 1024>>>();
    k_select<<<dim3(gb, EXPERTS), tb>>>(B);
    k_resolve<<<EXPERTS, 256>>>();
    k_invm<<<gb, tb>>>(B);

    cudaFuncSetAttribute(k_mlp, cudaFuncAttributeMaxDynamicSharedMemorySize, SMEM_TOTAL);
    int mtiles = (Mv + BM - 1)/BM;
    k_mlp<<<dim3(mtiles, EXPERTS), 256, SMEM_TOTAL>>>(feat, W1, b1, W2, b2, out, Mv);
}

// round 9
// speedup vs baseline: 1.9597x; 1.1321x over previous
#include <cuda_runtime.h>
#include <cuda_fp16.h>
#include <cstdint>

#define EXPERTS 16
#define FDIM 128
#define HDIM 256
#define ODIM 64
#define BMAX 262144
#define MMAX (BMAX/EXPERTS)
#define EQCAP 8192
#define BM 128

// ---------------- scratch ----------------
__device__ unsigned g_keys[(size_t)EXPERTS * BMAX];
__device__ unsigned g_hist[EXPERTS * 65536];
__device__ unsigned g_hist2[EXPERTS * 65536];
__device__ unsigned g_b16[EXPERTS];
__device__ unsigned g_rankInB[EXPERTS];
__device__ unsigned g_T[EXPERTS];
__device__ unsigned g_needEq[EXPERTS];
__device__ int      g_eqList[EXPERTS * EQCAP];
__device__ int      g_eqCnt[EXPERTS];
__device__ unsigned g_selMask[BMAX];
__device__ int      g_idx[EXPERTS * MMAX];
__device__ int      g_idxCnt[EXPERTS];
__device__ float    g_invm[BMAX];

// ---------------- helpers ----------------
__device__ __forceinline__ uint32_t smem_u32(const void* p) {
    uint32_t a;
    asm("{ .reg .u64 t; cvta.to.shared.u64 t, %1; cvt.u32.u64 %0, t; }" : "=r"(a) : "l"(p));
    return a;
}
#define LDSM_X4(r0,r1,r2,r3, addr) \
    asm volatile("ldmatrix.sync.aligned.m8n8.x4.shared.b16 {%0,%1,%2,%3}, [%4];" \
        : "=r"(r0),"=r"(r1),"=r"(r2),"=r"(r3) : "r"(addr))
#define MMA16816(d, a, b) \
    asm volatile("mma.sync.aligned.m16n8k16.row.col.f32.f16.f16.f32 " \
        "{%0,%1,%2,%3}, {%4,%5,%6,%7}, {%8,%9}, {%0,%1,%2,%3};" \
        : "+f"((d)[0]),"+f"((d)[1]),"+f"((d)[2]),"+f"((d)[3]) \
        : "r"((a)[0]),"r"((a)[1]),"r"((a)[2]),"r"((a)[3]), "r"((b)[0]),"r"((b)[1]))

// fp16 hi/lo split: hi+lo represents x to ~2^-22 relative
__device__ __forceinline__ void splitH2(float x0, float x1, unsigned &hw, unsigned &lw) {
    __half h0 = __float2half(x0), h1 = __float2half(x1);
    __half l0 = __float2half(x0 - __half2float(h0));
    __half l1 = __float2half(x1 - __half2float(h1));
    hw = (unsigned)__half_as_ushort(h0) | ((unsigned)__half_as_ushort(h1) << 16);
    lw = (unsigned)__half_as_ushort(l0) | ((unsigned)__half_as_ushort(l1) << 16);
}
__device__ __forceinline__ void splitH8(const float* x, uint4& vh, uint4& vl) {
    unsigned h0,h1,h2,h3,l0,l1,l2,l3;
    splitH2(x[0],x[1],h0,l0); splitH2(x[2],x[3],h1,l1);
    splitH2(x[4],x[5],h2,l2); splitH2(x[6],x[7],h3,l3);
    vh = make_uint4(h0,h1,h2,h3); vl = make_uint4(l0,l1,l2,l3);
}
// single fp16 round of 8 floats -> uint4
__device__ __forceinline__ void cvtH8(const float* x, uint4& vh) {
    unsigned w[4];
#pragma unroll
    for (int i=0;i<4;i++){
        __half a = __float2half(x[i*2]), b = __float2half(x[i*2+1]);
        w[i] = (unsigned)__half_as_ushort(a) | ((unsigned)__half_as_ushort(b) << 16);
    }
    vh = make_uint4(w[0],w[1],w[2],w[3]);
}
// XOR swizzle: 16B chunk index xored with (row&7); 256B rows
__device__ __forceinline__ unsigned swz(int row, int chunk) {
    return (unsigned)(row*256 + ((chunk ^ (row&7)) << 4));
}

// ---------------- K1: gate scores (exact fp32) ----------------
__global__ void k_scores(const float* __restrict__ feat, const float* __restrict__ Wg,
                         const float* __restrict__ bg, int B)
{
    __shared__ float sW[EXPERTS*FDIM];
    __shared__ float sb[EXPERTS];
    for (int i = threadIdx.x; i < EXPERTS*FDIM; i += blockDim.x) sW[i] = Wg[i];
    if (threadIdx.x < EXPERTS) sb[threadIdx.x] = bg[threadIdx.x];
    __syncthreads();
    int b = blockIdx.x*blockDim.x + threadIdx.x;
    if (b >= B) return;
    const float4* row = reinterpret_cast<const float4*>(feat + (size_t)b*FDIM);
    float acc[EXPERTS];
#pragma unroll
    for (int e=0;e<EXPERTS;e++) acc[e] = sb[e];
#pragma unroll 4
    for (int j=0;j<FDIM/4;j++){
        float4 x = row[j];
#pragma unroll
        for (int e=0;e<EXPERTS;e++){
            float4 w = *reinterpret_cast<const float4*>(&sW[e*FDIM + j*4]);
            acc[e] += x.x*w.x + x.y*w.y + x.z*w.z + x.w*w.w;
        }
    }
#pragma unroll
    for (int e=0;e<EXPERTS;e++){
        unsigned u = __float_as_uint(acc[e]);
        u = (u & 0x80000000u) ? ~u : (u | 0x80000000u);
        g_keys[(size_t)e*B + b] = u;
        atomicAdd(&g_hist[e*65536 + (u>>16)], 1u);
    }
}

// ---------------- descending scan over 65536 bins ----------------
__device__ __forceinline__ void scan_find(const unsigned* __restrict__ hist, unsigned target,
                                          unsigned* out_bin, unsigned* out_rank)
{
    int t = threadIdx.x;
    const uint4* h4 = reinterpret_cast<const uint4*>(hist);
    int base4 = 16384 - 16*(t+1);
    unsigned s = 0;
#pragma unroll
    for (int i=0;i<16;i++){ uint4 v = h4[base4+i]; s += v.x+v.y+v.z+v.w; }
    __shared__ unsigned warpSum[32], warpPre[32];
    unsigned lane = t & 31, wid = t >> 5;
    unsigned inc = s;
#pragma unroll
    for (int o=1;o<32;o<<=1){ unsigned n = __shfl_up_sync(~0u, inc, o); if (lane >= o) inc += n; }
    if (lane == 31) warpSum[wid] = inc;
    __syncthreads();
    if (wid == 0){
        unsigned ws = warpSum[lane], winc = ws;
#pragma unroll
        for (int o=1;o<32;o<<=1){ unsigned n = __shfl_up_sync(~0u, winc, o); if (lane >= o) winc += n; }
        warpPre[lane] = winc - ws;
    }
    __syncthreads();
    unsigned before = warpPre[wid] + inc - s;
    unsigned after  = before + s;
    if (before < target && target <= after){
        unsigned acc = before;
        int hi = 65535 - 64*t;
        for (int b = hi; b > hi-64; --b){
            unsigned cnt = hist[b];
            if (acc + cnt >= target){ *out_bin = (unsigned)b; *out_rank = target - acc; break; }
            acc += cnt;
        }
    }
}

__global__ void k_findbucket(int Mv){
    int e = blockIdx.x;
    scan_find(g_hist + e*65536, (unsigned)Mv, &g_b16[e], &g_rankInB[e]);
}
__global__ void k_findthresh2(){
    int e = blockIdx.x;
    __shared__ unsigned sBin, sRank;
    if (threadIdx.x == 0){ sBin = 0xFFFFFFFFu; sRank = 0; }
    __syncthreads();
    scan_find(g_hist2 + e*65536, g_rankInB[e], &sBin, &sRank);
    __syncthreads();
    if (threadIdx.x == 0){
        g_T[e] = (g_b16[e] << 16) | sBin;
        g_needEq[e] = sRank;
    }
}

__global__ void k_hist2(int B){
    int e = blockIdx.y;
    int i = blockIdx.x*blockDim.x + threadIdx.x;
    if (i >= B) return;
    unsigned u = g_keys[(size_t)e*B + i];
    if ((u >> 16) == g_b16[e]) atomicAdd(&g_hist2[e*65536 + (u & 0xFFFFu)], 1u);
}

__global__ void k_select(int B){
    int e = blockIdx.y;
    int i = blockIdx.x*blockDim.x + threadIdx.x;
    int lane = threadIdx.x & 31;
    bool inb = (i < B);
    unsigned u = inb ? g_keys[(size_t)e*B + i] : 0u;
    unsigned t = g_T[e];
    bool gt = inb && (u > t);
    unsigned mask = __ballot_sync(~0u, gt);
    if (mask){
        int leader = __ffs(mask) - 1;
        int base = 0;
        if (lane == leader) base = atomicAdd(&g_idxCnt[e], __popc(mask));
        base = __shfl_sync(~0u, base, leader);
        if (gt){
            int p = base + __popc(mask & ((1u << lane) - 1u));
            g_idx[e*MMAX + p] = i;
            atomicOr(&g_selMask[i], 1u << e);
        }
    }
    if (inb && u == t){
        int p = atomicAdd(&g_eqCnt[e], 1);
        if (p < EQCAP) g_eqList[e*EQCAP + p] = i;
    }
}

__global__ void k_resolve(){
    int e = blockIdx.x;
    int n = g_eqCnt[e]; if (n > EQCAP) n = EQCAP;
    int need = (int)g_needEq[e];
    for (int j = threadIdx.x; j < n; j += blockDim.x){
        int v = g_eqList[e*EQCAP + j];
        int r = 0;
        for (int k=0;k<n;k++) r += (g_eqList[e*EQCAP + k] < v);
        if (r < need){
            int p = atomicAdd(&g_idxCnt[e], 1);
            g_idx[e*MMAX + p] = v;
            atomicOr(&g_selMask[v], 1u << e);
        }
    }
}

__global__ void k_invm(int B){
    int i = blockIdx.x*blockDim.x + threadIdx.x;
    if (i>=B) return;
    int c = __popc(g_selMask[i]);
    g_invm[i] = 1.0f / (float)(c > 0 ? c : 1);
}

// ---------------- K8: mma.sync fp16x2 fused MLP ----------------
// activations split hi/lo fp16; weights single fp16 (error = weight rounding ~2^-11)
#define HDR_IDX   0       // 128 ints
#define HDR_INVM  512     // 128 floats
#define HDR_B1    1024    // 256 floats
#define HDR_B2    2048    // 64 floats
#define POOL      2560
#define OFF_XH  (POOL + 0)        // X hi [128 x 128] fp16  32KB
#define OFF_XL  (POOL + 32768)    // X lo                   32KB
#define OFF_W1  (POOL + 65536)    // W1 half [128 x 128]    32KB
#define OFF_HH  (POOL + 98304)    // H half hi [128 x 128]  32KB
#define OFF_HL  (POOL + 131072)   // H half lo              32KB
#define OFF_W2  (POOL + 163840)   // W2 half [64 x 128]     16KB
#define SMEM_TOTAL (POOL + 180224)   // 182784 bytes

__global__ __launch_bounds__(256, 1)
void k_mlp(const float* __restrict__ feat,
           const float* __restrict__ W1, const float* __restrict__ b1,
           const float* __restrict__ W2, const float* __restrict__ b2,
           float* __restrict__ out, int Mv)
{
    extern __shared__ char smem[];
    uint32_t sbase = smem_u32(smem);
    int tid = threadIdx.x, lane = tid & 31, wid = tid >> 5;
    int e = blockIdx.y;
    int slot0 = blockIdx.x * BM;

    int*   sIdx  = (int*)(smem + HDR_IDX);
    float* sInvm = (float*)(smem + HDR_INVM);
    float* sB1   = (float*)(smem + HDR_B1);
    float* sB2   = (float*)(smem + HDR_B2);

    if (tid < BM){
        int s = slot0 + tid;
        int t = (s < Mv) ? g_idx[e*MMAX + s] : 0;
        sIdx[tid]  = t;
        sInvm[tid] = (s < Mv) ? g_invm[t] : 0.0f;
    }
    sB1[tid] = b1[e*HDIM + tid];
    if (tid < ODIM) sB2[tid] = b2[e*ODIM + tid];
    __syncthreads();

    // ---- gather X [128 tokens x 128 f], fp16 hi/lo split, swizzled ----
#pragma unroll
    for (int it=0; it<8; ++it){
        int s = it*256 + tid;
        int row = s >> 4, cg = s & 15;
        const float* src = feat + (size_t)sIdx[row]*FDIM + cg*8;
        float x[8];
        *(float4*)&x[0] = *(const float4*)(src);
        *(float4*)&x[4] = *(const float4*)(src+4);
        uint4 vh, vl; splitH8(x, vh, vl);
        unsigned off = swz(row, cg);
        *(uint4*)(smem + OFF_XH + off) = vh;
        *(uint4*)(smem + OFF_XL + off) = vl;
    }

    int wm = wid & 1, wn = wid >> 1;     // 2 x 4 warp grid
    int m0 = wm * 64;

    float c2[4][2][4];
#pragma unroll
    for (int a=0;a<4;a++)
#pragma unroll
        for (int bb=0;bb<2;bb++)
#pragma unroll
            for (int i=0;i<4;i++) c2[a][bb][i] = 0.0f;

    for (int h=0; h<2; ++h){
        __syncthreads();
        // load W1 half [128 x 128] -> single fp16
#pragma unroll
        for (int it=0; it<8; ++it){
            int s = it*256 + tid;
            int row = s >> 4, cg = s & 15;
            const float* src = W1 + ((size_t)e*HDIM + h*128 + row)*FDIM + cg*8;
            float x[8];
            *(float4*)&x[0] = *(const float4*)(src);
            *(float4*)&x[4] = *(const float4*)(src+4);
            uint4 vh; cvtH8(x, vh);
            *(uint4*)(smem + OFF_W1 + swz(row, cg)) = vh;
        }
        // load W2 half [64 x 128] -> single fp16
#pragma unroll
        for (int it=0; it<4; ++it){
            int s = it*256 + tid;
            int row = s >> 4, cg = s & 15;
            const float* src = W2 + ((size_t)e*ODIM + row)*HDIM + h*128 + cg*8;
            float x[8];
            *(float4*)&x[0] = *(const float4*)(src);
            *(float4*)&x[4] = *(const float4*)(src+4);
            uint4 vh; cvtH8(x, vh);
            *(uint4*)(smem + OFF_W2 + swz(row, cg)) = vh;
        }
        __syncthreads();

        // ---- GEMM1 half: C1[128,128] = (Xhi + Xlo) * W1half^T ----
        float c1[4][4][4];
#pragma unroll
        for (int a=0;a<4;a++)
#pragma unroll
            for (int bb=0;bb<4;bb++)
#pragma unroll
                for (int i=0;i<4;i++) c1[a][bb][i] = 0.0f;

#pragma unroll 1
        for (int ks=0; ks<8; ++ks){
            uint32_t ah[4][4], al[4][4];
            int arow_l = lane & 15, achk = ks*2 + (lane >> 4);
#pragma unroll
            for (int mt=0; mt<4; ++mt){
                int row = m0 + mt*16 + arow_l;
                unsigned off = swz(row, achk);
                LDSM_X4(ah[mt][0],ah[mt][1],ah[mt][2],ah[mt][3], sbase + OFF_XH + off);
                LDSM_X4(al[mt][0],al[mt][1],al[mt][2],al[mt][3], sbase + OFF_XL + off);
            }
            uint32_t bh[4][2];
            int brow_l = (lane & 7) + ((lane >> 4) << 3);
            int bchk = ks*2 + ((lane >> 3) & 1);
#pragma unroll
            for (int np=0; np<2; ++np){
                int nrow = wn*32 + np*16 + brow_l;
                unsigned off = swz(nrow, bchk);
                uint32_t t0,t1,t2,t3;
                LDSM_X4(t0,t1,t2,t3, sbase + OFF_W1 + off);
                bh[np*2][0]=t0; bh[np*2][1]=t1; bh[np*2+1][0]=t2; bh[np*2+1][1]=t3;
            }
#pragma unroll
            for (int mt=0; mt<4; ++mt)
#pragma unroll
                for (int nf=0; nf<4; ++nf){
                    MMA16816(c1[mt][nf], ah[mt], bh[nf]);
                    MMA16816(c1[mt][nf], al[mt], bh[nf]);
                }
        }

        // epilogue1: +b1, relu, split fp16 -> H half smem
#pragma unroll
        for (int mt=0; mt<4; ++mt)
#pragma unroll
            for (int nf=0; nf<4; ++nf)
#pragma unroll
                for (int i2=0; i2<2; ++i2){
                    int row = m0 + mt*16 + (lane>>2) + 8*i2;
                    int col = wn*32 + nf*8 + (lane&3)*2;
                    float v0 = fmaxf(c1[mt][nf][i2*2+0] + sB1[h*128 + col],     0.0f);
                    float v1 = fmaxf(c1[mt][nf][i2*2+1] + sB1[h*128 + col + 1], 0.0f);
                    unsigned hw, lw; splitH2(v0, v1, hw, lw);
                    unsigned off = swz(row, col>>3) + (col&7)*2;
                    *(uint32_t*)(smem + OFF_HH + off) = hw;
                    *(uint32_t*)(smem + OFF_HL + off) = lw;
                }
        __syncthreads();

        // ---- GEMM2 partial: C2 += (Hhi + Hlo) * W2half^T ----
#pragma unroll 1
        for (int ks=0; ks<8; ++ks){
            uint32_t ah[4][4], al[4][4];
            int arow_l = lane & 15, achk = ks*2 + (lane >> 4);
#pragma unroll
            for (int mt=0; mt<4; ++mt){
                int row = m0 + mt*16 + arow_l;
                unsigned off = swz(row, achk);
                LDSM_X4(ah[mt][0],ah[mt][1],ah[mt][2],ah[mt][3], sbase + OFF_HH + off);
                LDSM_X4(al[mt][0],al[mt][1],al[mt][2],al[mt][3], sbase + OFF_HL + off);
            }
            uint32_t bh[2][2];
            {
                int nrow = wn*16 + (lane & 7) + ((lane >> 4) << 3);
                int bchk = ks*2 + ((lane >> 3) & 1);
                unsigned off = swz(nrow, bchk);
                uint32_t t0,t1,t2,t3;
                LDSM_X4(t0,t1,t2,t3, sbase + OFF_W2 + off);
                bh[0][0]=t0; bh[0][1]=t1; bh[1][0]=t2; bh[1][1]=t3;
            }
#pragma unroll
            for (int mt=0; mt<4; ++mt)
#pragma unroll
                for (int nf=0; nf<2; ++nf){
                    MMA16816(c2[mt][nf], ah[mt], bh[nf]);
                    MMA16816(c2[mt][nf], al[mt], bh[nf]);
                }
        }
    }

    // ---- final epilogue: +b2, x 1/m, scatter-add ----
#pragma unroll
    for (int mt=0; mt<4; ++mt)
#pragma unroll
        for (int nf=0; nf<2; ++nf)
#pragma unroll
            for (int i=0; i<4; ++i){
                int row = m0 + mt*16 + (lane>>2) + 8*(i>>1);
                int col = wn*16 + nf*8 + (lane&3)*2 + (i&1);
                int tkn = sIdx[row];
                float w = sInvm[row];
                atomicAdd(&out[(size_t)tkn*ODIM + col], (c2[mt][nf][i] + sB2[col]) * w);
            }
}

// ---------------- launch ----------------
extern "C" void kernel_launch(void* const* d_in, const int* in_sizes, int n_in,
                              void* d_out, int out_size)
{
    const float* feat = (const float*)d_in[0];
    const float* Wg   = (const float*)d_in[1];
    const float* bg   = (const float*)d_in[2];
    const float* W1   = (const float*)d_in[3];
    const float* b1   = (const float*)d_in[4];
    const float* W2   = (const float*)d_in[5];
    const float* b2   = (const float*)d_in[6];
    float* out = (float*)d_out;

    int B = in_sizes[0] / FDIM;
    int Mv = (B + EXPERTS - 1) / EXPERTS;
    if (Mv < 1) Mv = 1;
    if (Mv > B) Mv = B;

    void *p_hist, *p_hist2, *p_selMask, *p_eqCnt, *p_idxCnt;
    cudaGetSymbolAddress(&p_hist,    g_hist);
    cudaGetSymbolAddress(&p_hist2,   g_hist2);
    cudaGetSymbolAddress(&p_selMask, g_selMask);
    cudaGetSymbolAddress(&p_eqCnt,   g_eqCnt);
    cudaGetSymbolAddress(&p_idxCnt,  g_idxCnt);

    cudaMemsetAsync(p_hist,    0, (size_t)EXPERTS*65536*sizeof(unsigned), 0);
    cudaMemsetAsync(p_hist2,   0, (size_t)EXPERTS*65536*sizeof(unsigned), 0);
    cudaMemsetAsync(p_selMask, 0, (size_t)B*sizeof(unsigned), 0);
    cudaMemsetAsync(p_eqCnt,   0, (size_t)EXPERTS*sizeof(int), 0);
    cudaMemsetAsync(p_idxCnt,  0, (size_t)EXPERTS*sizeof(int), 0);
    cudaMemsetAsync(d_out,     0, (size_t)out_size*sizeof(float), 0);

    int tb = 256;
    int gb = (B + tb - 1)/tb;
    k_scores<<<gb, tb>>>(feat, Wg, bg, B);
    k_findbucket<<<EXPERTS, 1024>>>(Mv);
    k_hist2<<<dim3(gb, EXPERTS), tb>>>(B);
    k_findthresh2<<<EXPERTS, 1024>>>();
    k_select<<<dim3(gb, EXPERTS), tb>>>(B);
    k_resolve<<<EXPERTS, 256>>>();
    k_invm<<<gb, tb>>>(B);

    cudaFuncSetAttribute(k_mlp, cudaFuncAttributeMaxDynamicSharedMemorySize, SMEM_TOTAL);
    int mtiles = (Mv + BM - 1)/BM;
    k_mlp<<<dim3(mtiles, EXPERTS), 256, SMEM_TOTAL>>>(feat, W1, b1, W2, b2, out, Mv);
}

// round 12
// speedup vs baseline: 2.3428x; 1.1955x over previous
#include <cuda_runtime.h>
#include <cuda_fp16.h>
#include <cstdint>

#define EXPERTS 16
#define FDIM 128
#define HDIM 256
#define ODIM 64
#define BMAX 262144
#define MMAX (BMAX/EXPERTS)
#define EQCAP 8192
#define BM 128
#define NCTA 9

// ---------------- scratch ----------------
__device__ unsigned g_keys[(size_t)EXPERTS * BMAX];
__device__ unsigned g_hist[EXPERTS * 65536];
__device__ unsigned g_hist2[EXPERTS * 65536];
__device__ unsigned g_b16[EXPERTS];
__device__ unsigned g_rankInB[EXPERTS];
__device__ unsigned g_T[EXPERTS];
__device__ unsigned g_needEq[EXPERTS];
__device__ int      g_eqList[EXPERTS * EQCAP];
__device__ int      g_eqCnt[EXPERTS];
__device__ unsigned g_selMask[BMAX];
__device__ int      g_idx[EXPERTS * MMAX];
__device__ int      g_idxCnt[EXPERTS];
__device__ float    g_invm[BMAX];
__device__ __half   g_w1h[(size_t)EXPERTS * HDIM * FDIM];   // 1 MB fp16 weights
__device__ __half   g_w2h[(size_t)EXPERTS * ODIM * HDIM];   // 0.5 MB

// ---------------- helpers ----------------
__device__ __forceinline__ uint32_t smem_u32(const void* p) {
    uint32_t a;
    asm("{ .reg .u64 t; cvta.to.shared.u64 t, %1; cvt.u32.u64 %0, t; }" : "=r"(a) : "l"(p));
    return a;
}
#define LDSM_X4(r0,r1,r2,r3, addr) \
    asm volatile("ldmatrix.sync.aligned.m8n8.x4.shared.b16 {%0,%1,%2,%3}, [%4];" \
        : "=r"(r0),"=r"(r1),"=r"(r2),"=r"(r3) : "r"(addr))
#define MMA16816(d, a, b) \
    asm volatile("mma.sync.aligned.m16n8k16.row.col.f32.f16.f16.f32 " \
        "{%0,%1,%2,%3}, {%4,%5,%6,%7}, {%8,%9}, {%0,%1,%2,%3};" \
        : "+f"((d)[0]),"+f"((d)[1]),"+f"((d)[2]),"+f"((d)[3]) \
        : "r"((a)[0]),"r"((a)[1]),"r"((a)[2]),"r"((a)[3]), "r"((b)[0]),"r"((b)[1]))
#define CP_ASYNC16(dst, src) \
    asm volatile("cp.async.ca.shared.global [%0], [%1], 16;" :: "r"(dst), "l"(src) : "memory")
#define CP_COMMIT() asm volatile("cp.async.commit_group;" ::: "memory")
#define CP_WAIT0()  asm volatile("cp.async.wait_group 0;" ::: "memory")

__device__ __forceinline__ unsigned cvtH2(float a, float b) {
    __half ha = __float2half(a), hb = __float2half(b);
    return (unsigned)__half_as_ushort(ha) | ((unsigned)__half_as_ushort(hb) << 16);
}
__device__ __forceinline__ void cvtH8(const float* x, uint4& vh) {
    vh = make_uint4(cvtH2(x[0],x[1]), cvtH2(x[2],x[3]), cvtH2(x[4],x[5]), cvtH2(x[6],x[7]));
}
// XOR swizzle: 16B chunk index xored with (row&7); 256B rows
__device__ __forceinline__ unsigned swz(int row, int chunk) {
    return (unsigned)(row*256 + ((chunk ^ (row&7)) << 4));
}

// ---------------- K0: weights -> fp16 (once per launch) ----------------
__global__ void k_cvtw(const float* __restrict__ W1, const float* __restrict__ W2)
{
    int i4 = (blockIdx.x*blockDim.x + threadIdx.x) * 4;
    const int n1 = EXPERTS*HDIM*FDIM;     // 524288
    const int n2 = EXPERTS*ODIM*HDIM;     // 262144
    if (i4 < n1){
        float4 v = *reinterpret_cast<const float4*>(W1 + i4);
        *reinterpret_cast<uint2*>(g_w1h + i4) = make_uint2(cvtH2(v.x,v.y), cvtH2(v.z,v.w));
    } else if (i4 - n1 < n2){
        int j4 = i4 - n1;
        float4 v = *reinterpret_cast<const float4*>(W2 + j4);
        *reinterpret_cast<uint2*>(g_w2h + j4) = make_uint2(cvtH2(v.x,v.y), cvtH2(v.z,v.w));
    }
}

// ---------------- K1: gate scores (exact fp32) ----------------
__global__ void k_scores(const float* __restrict__ feat, const float* __restrict__ Wg,
                         const float* __restrict__ bg, int B)
{
    __shared__ float sW[EXPERTS*FDIM];
    __shared__ float sb[EXPERTS];
    for (int i = threadIdx.x; i < EXPERTS*FDIM; i += blockDim.x) sW[i] = Wg[i];
    if (threadIdx.x < EXPERTS) sb[threadIdx.x] = bg[threadIdx.x];
    __syncthreads();
    int b = blockIdx.x*blockDim.x + threadIdx.x;
    if (b >= B) return;
    const float4* row = reinterpret_cast<const float4*>(feat + (size_t)b*FDIM);
    float acc[EXPERTS];
#pragma unroll
    for (int e=0;e<EXPERTS;e++) acc[e] = sb[e];
#pragma unroll 4
    for (int j=0;j<FDIM/4;j++){
        float4 x = row[j];
#pragma unroll
        for (int e=0;e<EXPERTS;e++){
            float4 w = *reinterpret_cast<const float4*>(&sW[e*FDIM + j*4]);
            acc[e] += x.x*w.x + x.y*w.y + x.z*w.z + x.w*w.w;
        }
    }
#pragma unroll
    for (int e=0;e<EXPERTS;e++){
        unsigned u = __float_as_uint(acc[e]);
        u = (u & 0x80000000u) ? ~u : (u | 0x80000000u);
        g_keys[(size_t)e*B + b] = u;
        atomicAdd(&g_hist[e*65536 + (u>>16)], 1u);
    }
}

// ---------------- descending scan over 65536 bins ----------------
__device__ __forceinline__ void scan_find(const unsigned* __restrict__ hist, unsigned target,
                                          unsigned* out_bin, unsigned* out_rank)
{
    int t = threadIdx.x;
    const uint4* h4 = reinterpret_cast<const uint4*>(hist);
    int base4 = 16384 - 16*(t+1);
    unsigned s = 0;
#pragma unroll
    for (int i=0;i<16;i++){ uint4 v = h4[base4+i]; s += v.x+v.y+v.z+v.w; }
    __shared__ unsigned warpSum[32], warpPre[32];
    unsigned lane = t & 31, wid = t >> 5;
    unsigned inc = s;
#pragma unroll
    for (int o=1;o<32;o<<=1){ unsigned n = __shfl_up_sync(~0u, inc, o); if (lane >= o) inc += n; }
    if (lane == 31) warpSum[wid] = inc;
    __syncthreads();
    if (wid == 0){
        unsigned ws = warpSum[lane], winc = ws;
#pragma unroll
        for (int o=1;o<32;o<<=1){ unsigned n = __shfl_up_sync(~0u, winc, o); if (lane >= o) winc += n; }
        warpPre[lane] = winc - ws;
    }
    __syncthreads();
    unsigned before = warpPre[wid] + inc - s;
    unsigned after  = before + s;
    if (before < target && target <= after){
        unsigned acc = before;
        int hi = 65535 - 64*t;
        for (int b = hi; b > hi-64; --b){
            unsigned cnt = hist[b];
            if (acc + cnt >= target){ *out_bin = (unsigned)b; *out_rank = target - acc; break; }
            acc += cnt;
        }
    }
}

__global__ void k_findbucket(int Mv){
    int e = blockIdx.x;
    scan_find(g_hist + e*65536, (unsigned)Mv, &g_b16[e], &g_rankInB[e]);
}
__global__ void k_findthresh2(){
    int e = blockIdx.x;
    __shared__ unsigned sBin, sRank;
    if (threadIdx.x == 0){ sBin = 0xFFFFFFFFu; sRank = 0; }
    __syncthreads();
    scan_find(g_hist2 + e*65536, g_rankInB[e], &sBin, &sRank);
    __syncthreads();
    if (threadIdx.x == 0){
        g_T[e] = (g_b16[e] << 16) | sBin;
        g_needEq[e] = sRank;
    }
}

__global__ void k_hist2(int B){
    int e = blockIdx.y;
    int i = blockIdx.x*blockDim.x + threadIdx.x;
    if (i >= B) return;
    unsigned u = g_keys[(size_t)e*B + i];
    if ((u >> 16) == g_b16[e]) atomicAdd(&g_hist2[e*65536 + (u & 0xFFFFu)], 1u);
}

__global__ void k_select(int B){
    int e = blockIdx.y;
    int i = blockIdx.x*blockDim.x + threadIdx.x;
    int lane = threadIdx.x & 31;
    bool inb = (i < B);
    unsigned u = inb ? g_keys[(size_t)e*B + i] : 0u;
    unsigned t = g_T[e];
    bool gt = inb && (u > t);
    unsigned mask = __ballot_sync(~0u, gt);
    if (mask){
        int leader = __ffs(mask) - 1;
        int base = 0;
        if (lane == leader) base = atomicAdd(&g_idxCnt[e], __popc(mask));
        base = __shfl_sync(~0u, base, leader);
        if (gt){
            int p = base + __popc(mask & ((1u << lane) - 1u));
            g_idx[e*MMAX + p] = i;
            atomicOr(&g_selMask[i], 1u << e);
        }
    }
    if (inb && u == t){
        int p = atomicAdd(&g_eqCnt[e], 1);
        if (p < EQCAP) g_eqList[e*EQCAP + p] = i;
    }
}

__global__ void k_resolve(){
    int e = blockIdx.x;
    int n = g_eqCnt[e]; if (n > EQCAP) n = EQCAP;
    int need = (int)g_needEq[e];
    for (int j = threadIdx.x; j < n; j += blockDim.x){
        int v = g_eqList[e*EQCAP + j];
        int r = 0;
        for (int k=0;k<n;k++) r += (g_eqList[e*EQCAP + k] < v);
        if (r < need){
            int p = atomicAdd(&g_idxCnt[e], 1);
            g_idx[e*MMAX + p] = v;
            atomicOr(&g_selMask[v], 1u << e);
        }
    }
}

__global__ void k_invm(int B){
    int i = blockIdx.x*blockDim.x + threadIdx.x;
    if (i>=B) return;
    int c = __popc(g_selMask[i]);
    g_invm[i] = 1.0f / (float)(c > 0 ? c : 1);
}

// ---------------- K8: persistent-expert fp16 mma MLP with cp.async X pipeline ----------------
#define HDR_IDXA  0        // 128 ints
#define HDR_IDXB  512      // 128 ints
#define HDR_B1    1024     // 256 floats
#define HDR_B2    2048     // 64 floats
#define POOL      2304
#define OFF_W1    (POOL + 0)        // W1 fp16 [2 halves][128 x 128]  64KB
#define OFF_W2    (POOL + 65536)    // W2 fp16 [2 halves][64 x 128]   32KB
#define OFF_X     (POOL + 98304)    // X  fp16 [128 x 128]            32KB
#define OFF_H     (POOL + 131072)   // H  fp16 [128 x 128]            32KB
#define OFF_STAGE (POOL + 163840)   // X staging fp32 [128 x 512B]    64KB
#define SMEM_TOTAL (POOL + 229376)  // 231,680 bytes

__global__ __launch_bounds__(256, 1)
void k_mlp(const float* __restrict__ feat,
           const float* __restrict__ b1, const float* __restrict__ b2,
           float* __restrict__ out, int Mv)
{
    extern __shared__ char smem[];
    uint32_t sbase = smem_u32(smem);
    int tid = threadIdx.x, lane = tid & 31, wid = tid >> 5;
    int e = blockIdx.y;
    int ntiles = (Mv + BM - 1) / BM;

    float* sB1 = (float*)(smem + HDR_B1);
    float* sB2 = (float*)(smem + HDR_B2);
    int* bufs[2] = { (int*)(smem + HDR_IDXA), (int*)(smem + HDR_IDXB) };

    sB1[tid] = b1[e*HDIM + tid];
    if (tid < ODIM) sB2[tid] = b2[e*ODIM + tid];

    // prologue: indices + async gather for first tile, then weights
    int t0 = blockIdx.x;
    if (t0 < ntiles && tid < BM){
        int slot = t0*BM + tid;
        bufs[0][tid] = (slot < Mv) ? g_idx[e*MMAX + slot] : 0;
    }
    __syncthreads();
    if (t0 < ntiles){
        const int* sI = bufs[0];
#pragma unroll
        for (int it=0; it<8; ++it){
            int s = it*256 + tid, row = s >> 4, cg = s & 15;
            const float* src = feat + (size_t)sI[row]*FDIM + cg*8;
            uint32_t dst = sbase + OFF_STAGE + row*512 + cg*32;
            CP_ASYNC16(dst, src);
            CP_ASYNC16(dst+16, src+4);
        }
    }
    CP_COMMIT();

    // load fp16 weights once (L2-resident, pre-converted)
#pragma unroll
    for (int it=0; it<16; ++it){
        int s = it*256 + tid, row = s >> 4, cg = s & 15;
        uint4 v = *reinterpret_cast<const uint4*>(g_w1h + (size_t)(e*HDIM + row)*FDIM + cg*8);
        *(uint4*)(smem + OFF_W1 + (row>>7)*32768 + swz(row&127, cg)) = v;
    }
#pragma unroll
    for (int it=0; it<8; ++it){
        int s = it*256 + tid, row = s >> 5, cgg = s & 31;
        uint4 v = *reinterpret_cast<const uint4*>(g_w2h + (size_t)(e*ODIM + row)*HDIM + cgg*8);
        *(uint4*)(smem + OFF_W2 + (cgg>>4)*16384 + swz(row, cgg&15)) = v;
    }

    int wm = wid & 1, wn = wid >> 1;   // 2 x 4 warp grid
    int m0 = wm * 64;
    int curbuf = 0;

    for (int t = t0; t < ntiles; t += NCTA){
        int* sIdxC = bufs[curbuf];
        int* sIdxN = bufs[curbuf ^ 1];

        CP_WAIT0();
        __syncthreads();                      // staging ready; prior tile fully consumed

        // convert staging -> X fp16 (swizzled)
#pragma unroll
        for (int it=0; it<8; ++it){
            int s = it*256 + tid, row = s >> 4, cg = s & 15;
            const float* st = (const float*)(smem + OFF_STAGE + row*512 + cg*32);
            float x[8];
            *(float4*)&x[0] = *(const float4*)st;
            *(float4*)&x[4] = *(const float4*)(st+4);
            uint4 vh; cvtH8(x, vh);
            *(uint4*)(smem + OFF_X + swz(row, cg)) = vh;
        }

        // prep next tile indices
        int tn = t + NCTA;
        if (tn < ntiles && tid < BM){
            int slot = tn*BM + tid;
            sIdxN[tid] = (slot < Mv) ? g_idx[e*MMAX + slot] : 0;
        }
        __syncthreads();                      // X ready; staging free; sIdxN ready

        // kick async gather for next tile (overlaps compute below)
        if (tn < ntiles){
#pragma unroll
            for (int it=0; it<8; ++it){
                int s = it*256 + tid, row = s >> 4, cg = s & 15;
                const float* src = feat + (size_t)sIdxN[row]*FDIM + cg*8;
                uint32_t dst = sbase + OFF_STAGE + row*512 + cg*32;
                CP_ASYNC16(dst, src);
                CP_ASYNC16(dst+16, src+4);
            }
        }
        CP_COMMIT();

        float c2[4][2][4];
#pragma unroll
        for (int a=0;a<4;a++)
#pragma unroll
            for (int bb=0;bb<2;bb++)
#pragma unroll
                for (int i=0;i<4;i++) c2[a][bb][i] = 0.0f;

#pragma unroll 1
        for (int h=0; h<2; ++h){
            // ---- GEMM1 half: C1 = X * W1half^T ----
            float c1[4][4][4];
#pragma unroll
            for (int a=0;a<4;a++)
#pragma unroll
                for (int bb=0;bb<4;bb++)
#pragma unroll
                    for (int i=0;i<4;i++) c1[a][bb][i] = 0.0f;

#pragma unroll 1
            for (int ks=0; ks<8; ++ks){
                uint32_t ah[4][4];
                int arow_l = lane & 15, achk = ks*2 + (lane >> 4);
#pragma unroll
                for (int mt=0; mt<4; ++mt){
                    int row = m0 + mt*16 + arow_l;
                    LDSM_X4(ah[mt][0],ah[mt][1],ah[mt][2],ah[mt][3],
                            sbase + OFF_X + swz(row, achk));
                }
                uint32_t bh[4][2];
                int brow_l = (lane & 7) + ((lane >> 4) << 3);
                int bchk = ks*2 + ((lane >> 3) & 1);
#pragma unroll
                for (int np=0; np<2; ++np){
                    int nrow = wn*32 + np*16 + brow_l;
                    uint32_t t0r,t1r,t2r,t3r;
                    LDSM_X4(t0r,t1r,t2r,t3r,
                            sbase + OFF_W1 + h*32768 + swz(nrow, bchk));
                    bh[np*2][0]=t0r; bh[np*2][1]=t1r; bh[np*2+1][0]=t2r; bh[np*2+1][1]=t3r;
                }
#pragma unroll
                for (int mt=0; mt<4; ++mt)
#pragma unroll
                    for (int nf=0; nf<4; ++nf)
                        MMA16816(c1[mt][nf], ah[mt], bh[nf]);
            }

            // epilogue1: +b1, relu -> H fp16
#pragma unroll
            for (int mt=0; mt<4; ++mt)
#pragma unroll
                for (int nf=0; nf<4; ++nf)
#pragma unroll
                    for (int i2=0; i2<2; ++i2){
                        int row = m0 + mt*16 + (lane>>2) + 8*i2;
                        int col = wn*32 + nf*8 + (lane&3)*2;
                        float v0 = fmaxf(c1[mt][nf][i2*2+0] + sB1[h*128 + col],     0.0f);
                        float v1 = fmaxf(c1[mt][nf][i2*2+1] + sB1[h*128 + col + 1], 0.0f);
                        *(uint32_t*)(smem + OFF_H + swz(row, col>>3) + (col&7)*2) = cvtH2(v0, v1);
                    }
            __syncthreads();                  // H ready

            // ---- GEMM2 partial: C2 += H * W2half^T ----
#pragma unroll 1
            for (int ks=0; ks<8; ++ks){
                uint32_t ah[4][4];
                int arow_l = lane & 15, achk = ks*2 + (lane >> 4);
#pragma unroll
                for (int mt=0; mt<4; ++mt){
                    int row = m0 + mt*16 + arow_l;
                    LDSM_X4(ah[mt][0],ah[mt][1],ah[mt][2],ah[mt][3],
                            sbase + OFF_H + swz(row, achk));
                }
                uint32_t bh[2][2];
                {
                    int nrow = wn*16 + (lane & 7) + ((lane >> 4) << 3);
                    int bchk = ks*2 + ((lane >> 3) & 1);
                    uint32_t t0r,t1r,t2r,t3r;
                    LDSM_X4(t0r,t1r,t2r,t3r,
                            sbase + OFF_W2 + h*16384 + swz(nrow, bchk));
                    bh[0][0]=t0r; bh[0][1]=t1r; bh[1][0]=t2r; bh[1][1]=t3r;
                }
#pragma unroll
                for (int mt=0; mt<4; ++mt)
#pragma unroll
                    for (int nf=0; nf<2; ++nf)
                        MMA16816(c2[mt][nf], ah[mt], bh[nf]);
            }
            __syncthreads();                  // H free for next half / next tile
        }

        // ---- scatter: +b2, x 1/m, atomicAdd ----
#pragma unroll
        for (int mt=0; mt<4; ++mt)
#pragma unroll
            for (int nf=0; nf<2; ++nf)
#pragma unroll
                for (int i=0; i<4; ++i){
                    int row = m0 + mt*16 + (lane>>2) + 8*(i>>1);
                    int col = wn*16 + nf*8 + (lane&3)*2 + (i&1);
                    int tk  = sIdxC[row];
                    float w = ((t*BM + row) < Mv) ? g_invm[tk] : 0.0f;
                    atomicAdd(&out[(size_t)tk*ODIM + col], (c2[mt][nf][i] + sB2[col]) * w);
                }

        curbuf ^= 1;
    }
}

// ---------------- launch ----------------
extern "C" void kernel_launch(void* const* d_in, const int* in_sizes, int n_in,
                              void* d_out, int out_size)
{
    const float* feat = (const float*)d_in[0];
    const float* Wg   = (const float*)d_in[1];
    const float* bg   = (const float*)d_in[2];
    const float* W1   = (const float*)d_in[3];
    const float* b1   = (const float*)d_in[4];
    const float* W2   = (const float*)d_in[5];
    const float* b2   = (const float*)d_in[6];
    float* out = (float*)d_out;

    int B = in_sizes[0] / FDIM;
    int Mv = (B + EXPERTS - 1) / EXPERTS;
    if (Mv < 1) Mv = 1;
    if (Mv > B) Mv = B;

    void *p_hist, *p_hist2, *p_selMask, *p_eqCnt, *p_idxCnt;
    cudaGetSymbolAddress(&p_hist,    g_hist);
    cudaGetSymbolAddress(&p_hist2,   g_hist2);
    cudaGetSymbolAddress(&p_selMask, g_selMask);
    cudaGetSymbolAddress(&p_eqCnt,   g_eqCnt);
    cudaGetSymbolAddress(&p_idxCnt,  g_idxCnt);

    cudaMemsetAsync(p_hist,    0, (size_t)EXPERTS*65536*sizeof(unsigned), 0);
    cudaMemsetAsync(p_hist2,   0, (size_t)EXPERTS*65536*sizeof(unsigned), 0);
    cudaMemsetAsync(p_selMask, 0, (size_t)B*sizeof(unsigned), 0);
    cudaMemsetAsync(p_eqCnt,   0, (size_t)EXPERTS*sizeof(int), 0);
    cudaMemsetAsync(p_idxCnt,  0, (size_t)EXPERTS*sizeof(int), 0);
    cudaMemsetAsync(d_out,     0, (size_t)out_size*sizeof(float), 0);

    int tb = 256;
    int gb = (B + tb - 1)/tb;
    k_cvtw<<<768, 256>>>(W1, W2);
    k_scores<<<gb, tb>>>(feat, Wg, bg, B);
    k_findbucket<<<EXPERTS, 1024>>>(Mv);
    k_hist2<<<dim3(gb, EXPERTS), tb>>>(B);
    k_findthresh2<<<EXPERTS, 1024>>>();
    k_select<<<dim3(gb, EXPERTS), tb>>>(B);
    k_resolve<<<EXPERTS, 256>>>();
    k_invm<<<gb, tb>>>(B);

    cudaFuncSetAttribute(k_mlp, cudaFuncAttributeMaxDynamicSharedMemorySize, SMEM_TOTAL);
    k_mlp<<<dim3(NCTA, EXPERTS), 256, SMEM_TOTAL>>>(feat, b1, b2, out, Mv);
}

// round 13
// speedup vs baseline: 2.3446x; 1.0008x over previous
#include <cuda_runtime.h>
#include <cuda_fp16.h>
#include <cstdint>

#define EXPERTS 16
#define FDIM 128
#define HDIM 256
#define ODIM 64
#define BMAX 262144
#define MMAX (BMAX/EXPERTS)
#define EQCAP 8192
#define BM 128
#define NCTA 9

// ---------------- scratch ----------------
struct ZeroBlk {
    unsigned hist[EXPERTS * 65536];
    unsigned hist2[EXPERTS * 65536];
    unsigned selMask[BMAX];
    int      eqCnt[EXPERTS];
    int      idxCnt[EXPERTS];
};
__device__ ZeroBlk  g_z;
__device__ unsigned g_keys[(size_t)EXPERTS * BMAX];
__device__ unsigned g_b16[EXPERTS];
__device__ unsigned g_rankInB[EXPERTS];
__device__ unsigned g_T[EXPERTS];
__device__ unsigned g_needEq[EXPERTS];
__device__ int      g_eqList[EXPERTS * EQCAP];
__device__ int      g_idx[EXPERTS * MMAX];
__device__ float    g_invm[BMAX];
__device__ __half   g_w1h[(size_t)EXPERTS * HDIM * FDIM];
__device__ __half   g_w2h[(size_t)EXPERTS * ODIM * HDIM];

// ---------------- helpers ----------------
__device__ __forceinline__ uint32_t smem_u32(const void* p) {
    uint32_t a;
    asm("{ .reg .u64 t; cvta.to.shared.u64 t, %1; cvt.u32.u64 %0, t; }" : "=r"(a) : "l"(p));
    return a;
}
#define LDSM_X4(r0,r1,r2,r3, addr) \
    asm volatile("ldmatrix.sync.aligned.m8n8.x4.shared.b16 {%0,%1,%2,%3}, [%4];" \
        : "=r"(r0),"=r"(r1),"=r"(r2),"=r"(r3) : "r"(addr))
#define MMA16816(d, a, b) \
    asm volatile("mma.sync.aligned.m16n8k16.row.col.f32.f16.f16.f32 " \
        "{%0,%1,%2,%3}, {%4,%5,%6,%7}, {%8,%9}, {%0,%1,%2,%3};" \
        : "+f"((d)[0]),"+f"((d)[1]),"+f"((d)[2]),"+f"((d)[3]) \
        : "r"((a)[0]),"r"((a)[1]),"r"((a)[2]),"r"((a)[3]), "r"((b)[0]),"r"((b)[1]))
#define CP_ASYNC16(dst, src) \
    asm volatile("cp.async.ca.shared.global [%0], [%1], 16;" :: "r"(dst), "l"(src) : "memory")
#define CP_COMMIT() asm volatile("cp.async.commit_group;" ::: "memory")
#define CP_WAIT0()  asm volatile("cp.async.wait_group 0;" ::: "memory")

__device__ __forceinline__ unsigned cvtH2(float a, float b) {
    __half ha = __float2half(a), hb = __float2half(b);
    return (unsigned)__half_as_ushort(ha) | ((unsigned)__half_as_ushort(hb) << 16);
}
__device__ __forceinline__ void cvtH8(const float* x, uint4& vh) {
    vh = make_uint4(cvtH2(x[0],x[1]), cvtH2(x[2],x[3]), cvtH2(x[4],x[5]), cvtH2(x[6],x[7]));
}
__device__ __forceinline__ unsigned swz(int row, int chunk) {
    return (unsigned)(row*256 + ((chunk ^ (row&7)) << 4));
}

// ---------------- K0: weights -> fp16 ----------------
__global__ void k_cvtw(const float* __restrict__ W1, const float* __restrict__ W2)
{
    int i4 = (blockIdx.x*blockDim.x + threadIdx.x) * 4;
    const int n1 = EXPERTS*HDIM*FDIM;
    const int n2 = EXPERTS*ODIM*HDIM;
    if (i4 < n1){
        float4 v = *reinterpret_cast<const float4*>(W1 + i4);
        *reinterpret_cast<uint2*>(g_w1h + i4) = make_uint2(cvtH2(v.x,v.y), cvtH2(v.z,v.w));
    } else if (i4 - n1 < n2){
        int j4 = i4 - n1;
        float4 v = *reinterpret_cast<const float4*>(W2 + j4);
        *reinterpret_cast<uint2*>(g_w2h + j4) = make_uint2(cvtH2(v.x,v.y), cvtH2(v.z,v.w));
    }
}

// ---------------- K1: gate scores (exact fp32) ----------------
__global__ void k_scores(const float* __restrict__ feat, const float* __restrict__ Wg,
                         const float* __restrict__ bg, int B)
{
    __shared__ float sW[EXPERTS*FDIM];
    __shared__ float sb[EXPERTS];
    for (int i = threadIdx.x; i < EXPERTS*FDIM; i += blockDim.x) sW[i] = Wg[i];
    if (threadIdx.x < EXPERTS) sb[threadIdx.x] = bg[threadIdx.x];
    __syncthreads();
    int b = blockIdx.x*blockDim.x + threadIdx.x;
    if (b >= B) return;
    const float4* row = reinterpret_cast<const float4*>(feat + (size_t)b*FDIM);
    float acc[EXPERTS];
#pragma unroll
    for (int e=0;e<EXPERTS;e++) acc[e] = sb[e];
#pragma unroll 4
    for (int j=0;j<FDIM/4;j++){
        float4 x = row[j];
#pragma unroll
        for (int e=0;e<EXPERTS;e++){
            float4 w = *reinterpret_cast<const float4*>(&sW[e*FDIM + j*4]);
            acc[e] += x.x*w.x + x.y*w.y + x.z*w.z + x.w*w.w;
        }
    }
#pragma unroll
    for (int e=0;e<EXPERTS;e++){
        unsigned u = __float_as_uint(acc[e]);
        u = (u & 0x80000000u) ? ~u : (u | 0x80000000u);
        g_keys[(size_t)e*B + b] = u;
        atomicAdd(&g_z.hist[e*65536 + (u>>16)], 1u);
    }
}

// ---------------- descending scan over 65536 bins ----------------
__device__ __forceinline__ void scan_find(const unsigned* __restrict__ hist, unsigned target,
                                          unsigned* out_bin, unsigned* out_rank)
{
    int t = threadIdx.x;
    const uint4* h4 = reinterpret_cast<const uint4*>(hist);
    int base4 = 16384 - 16*(t+1);
    unsigned s = 0;
#pragma unroll
    for (int i=0;i<16;i++){ uint4 v = h4[base4+i]; s += v.x+v.y+v.z+v.w; }
    __shared__ unsigned warpSum[32], warpPre[32];
    unsigned lane = t & 31, wid = t >> 5;
    unsigned inc = s;
#pragma unroll
    for (int o=1;o<32;o<<=1){ unsigned n = __shfl_up_sync(~0u, inc, o); if (lane >= o) inc += n; }
    if (lane == 31) warpSum[wid] = inc;
    __syncthreads();
    if (wid == 0){
        unsigned ws = warpSum[lane], winc = ws;
#pragma unroll
        for (int o=1;o<32;o<<=1){ unsigned n = __shfl_up_sync(~0u, winc, o); if (lane >= o) winc += n; }
        warpPre[lane] = winc - ws;
    }
    __syncthreads();
    unsigned before = warpPre[wid] + inc - s;
    unsigned after  = before + s;
    if (before < target && target <= after){
        unsigned acc = before;
        int hi = 65535 - 64*t;
        for (int b = hi; b > hi-64; --b){
            unsigned cnt = hist[b];
            if (acc + cnt >= target){ *out_bin = (unsigned)b; *out_rank = target - acc; break; }
            acc += cnt;
        }
    }
}

__global__ void k_findbucket(int Mv){
    int e = blockIdx.x;
    scan_find(g_z.hist + e*65536, (unsigned)Mv, &g_b16[e], &g_rankInB[e]);
}
__global__ void k_findthresh2(){
    int e = blockIdx.x;
    __shared__ unsigned sBin, sRank;
    if (threadIdx.x == 0){ sBin = 0xFFFFFFFFu; sRank = 0; }
    __syncthreads();
    scan_find(g_z.hist2 + e*65536, g_rankInB[e], &sBin, &sRank);
    __syncthreads();
    if (threadIdx.x == 0){
        g_T[e] = (g_b16[e] << 16) | sBin;
        g_needEq[e] = sRank;
    }
}

__global__ void k_hist2(int B){
    int e = blockIdx.y;
    int i = blockIdx.x*blockDim.x + threadIdx.x;
    if (i >= B) return;
    unsigned u = g_keys[(size_t)e*B + i];
    if ((u >> 16) == g_b16[e]) atomicAdd(&g_z.hist2[e*65536 + (u & 0xFFFFu)], 1u);
}

__global__ void k_select(int B){
    int e = blockIdx.y;
    int i = blockIdx.x*blockDim.x + threadIdx.x;
    int lane = threadIdx.x & 31;
    bool inb = (i < B);
    unsigned u = inb ? g_keys[(size_t)e*B + i] : 0u;
    unsigned t = g_T[e];
    bool gt = inb && (u > t);
    unsigned mask = __ballot_sync(~0u, gt);
    if (mask){
        int leader = __ffs(mask) - 1;
        int base = 0;
        if (lane == leader) base = atomicAdd(&g_z.idxCnt[e], __popc(mask));
        base = __shfl_sync(~0u, base, leader);
        if (gt){
            int p = base + __popc(mask & ((1u << lane) - 1u));
            g_idx[e*MMAX + p] = i;
            atomicOr(&g_z.selMask[i], 1u << e);
        }
    }
    if (inb && u == t){
        int p = atomicAdd(&g_z.eqCnt[e], 1);
        if (p < EQCAP) g_eqList[e*EQCAP + p] = i;
    }
}

__global__ void k_resolve(){
    int e = blockIdx.x;
    int n = g_z.eqCnt[e]; if (n > EQCAP) n = EQCAP;
    int need = (int)g_needEq[e];
    for (int j = threadIdx.x; j < n; j += blockDim.x){
        int v = g_eqList[e*EQCAP + j];
        int r = 0;
        for (int k=0;k<n;k++) r += (g_eqList[e*EQCAP + k] < v);
        if (r < need){
            int p = atomicAdd(&g_z.idxCnt[e], 1);
            g_idx[e*MMAX + p] = v;
            atomicOr(&g_z.selMask[v], 1u << e);
        }
    }
}

__global__ void k_invm(int B){
    int i = blockIdx.x*blockDim.x + threadIdx.x;
    if (i>=B) return;
    int c = __popc(g_z.selMask[i]);
    g_invm[i] = 1.0f / (float)(c > 0 ? c : 1);
}

// ---------------- K8: persistent-expert fp16 mma MLP ----------------
#define HDR_IDXA  0
#define HDR_IDXB  512
#define HDR_B1    1024
#define HDR_B2    2048
#define POOL      2304
#define OFF_W1    (POOL + 0)        // 64KB
#define OFF_W2    (POOL + 65536)    // 32KB
#define OFF_X     (POOL + 98304)    // 32KB
#define OFF_H     (POOL + 131072)   // 32KB
#define OFF_STAGE (POOL + 163840)   // 64KB
#define SMEM_TOTAL (POOL + 229376)  // 231,680 bytes

__global__ __launch_bounds__(256, 1)
void k_mlp(const float* __restrict__ feat,
           const float* __restrict__ b1, const float* __restrict__ b2,
           float* __restrict__ out, int Mv)
{
    extern __shared__ char smem[];
    uint32_t sbase = smem_u32(smem);
    int tid = threadIdx.x, lane = tid & 31, wid = tid >> 5;
    int e = blockIdx.y;
    int ntiles = (Mv + BM - 1) / BM;

    float* sB1 = (float*)(smem + HDR_B1);
    float* sB2 = (float*)(smem + HDR_B2);
    int* bufs[2] = { (int*)(smem + HDR_IDXA), (int*)(smem + HDR_IDXB) };

    sB1[tid] = b1[e*HDIM + tid];
    if (tid < ODIM) sB2[tid] = b2[e*ODIM + tid];

    int t0 = blockIdx.x;
    if (t0 < ntiles && tid < BM){
        int slot = t0*BM + tid;
        bufs[0][tid] = (slot < Mv) ? g_idx[e*MMAX + slot] : 0;
    }
    __syncthreads();
    if (t0 < ntiles){
        const int* sI = bufs[0];
#pragma unroll
        for (int it=0; it<8; ++it){
            int s = it*256 + tid, row = s >> 4, cg = s & 15;
            const float* src = feat + (size_t)sI[row]*FDIM + cg*8;
            uint32_t dst = sbase + OFF_STAGE + row*512 + cg*32;
            CP_ASYNC16(dst, src);
            CP_ASYNC16(dst+16, src+4);
        }
    }
    CP_COMMIT();

    // resident fp16 weights
#pragma unroll
    for (int it=0; it<16; ++it){
        int s = it*256 + tid, row = s >> 4, cg = s & 15;
        uint4 v = *reinterpret_cast<const uint4*>(g_w1h + (size_t)(e*HDIM + row)*FDIM + cg*8);
        *(uint4*)(smem + OFF_W1 + (row>>7)*32768 + swz(row&127, cg)) = v;
    }
#pragma unroll
    for (int it=0; it<8; ++it){
        int s = it*256 + tid, row = s >> 5, cgg = s & 31;
        uint4 v = *reinterpret_cast<const uint4*>(g_w2h + (size_t)(e*ODIM + row)*HDIM + cgg*8);
        *(uint4*)(smem + OFF_W2 + (cgg>>4)*16384 + swz(row, cgg&15)) = v;
    }

    int wm = wid & 1, wn = wid >> 1;
    int m0 = wm * 64;
    int curbuf = 0;

    for (int t = t0; t < ntiles; t += NCTA){
        int* sIdxC = bufs[curbuf];
        int* sIdxN = bufs[curbuf ^ 1];

        CP_WAIT0();
        __syncthreads();

        // staging -> X fp16 (swizzled)
#pragma unroll
        for (int it=0; it<8; ++it){
            int s = it*256 + tid, row = s >> 4, cg = s & 15;
            const float* st = (const float*)(smem + OFF_STAGE + row*512 + cg*32);
            float x[8];
            *(float4*)&x[0] = *(const float4*)st;
            *(float4*)&x[4] = *(const float4*)(st+4);
            uint4 vh; cvtH8(x, vh);
            *(uint4*)(smem + OFF_X + swz(row, cg)) = vh;
        }

        int tn = t + NCTA;
        if (tn < ntiles && tid < BM){
            int slot = tn*BM + tid;
            sIdxN[tid] = (slot < Mv) ? g_idx[e*MMAX + slot] : 0;
        }
        __syncthreads();

        if (tn < ntiles){
#pragma unroll
            for (int it=0; it<8; ++it){
                int s = it*256 + tid, row = s >> 4, cg = s & 15;
                const float* src = feat + (size_t)sIdxN[row]*FDIM + cg*8;
                uint32_t dst = sbase + OFF_STAGE + row*512 + cg*32;
                CP_ASYNC16(dst, src);
                CP_ASYNC16(dst+16, src+4);
            }
        }
        CP_COMMIT();

        float c2[4][2][4];
#pragma unroll
        for (int a=0;a<4;a++)
#pragma unroll
            for (int bb=0;bb<2;bb++)
#pragma unroll
                for (int i=0;i<4;i++) c2[a][bb][i] = 0.0f;

#pragma unroll 1
        for (int h=0; h<2; ++h){
            float c1[4][4][4];
#pragma unroll
            for (int a=0;a<4;a++)
#pragma unroll
                for (int bb=0;bb<4;bb++)
#pragma unroll
                    for (int i=0;i<4;i++) c1[a][bb][i] = 0.0f;

            // unroll 2: let ptxas overlap iter k+1 LDSMs under iter k MMAs
#pragma unroll 2
            for (int ks=0; ks<8; ++ks){
                uint32_t ah[4][4];
                int arow_l = lane & 15, achk = ks*2 + (lane >> 4);
#pragma unroll
                for (int mt=0; mt<4; ++mt){
                    int row = m0 + mt*16 + arow_l;
                    LDSM_X4(ah[mt][0],ah[mt][1],ah[mt][2],ah[mt][3],
                            sbase + OFF_X + swz(row, achk));
                }
                uint32_t bh[4][2];
                int brow_l = (lane & 7) + ((lane >> 4) << 3);
                int bchk = ks*2 + ((lane >> 3) & 1);
#pragma unroll
                for (int np=0; np<2; ++np){
                    int nrow = wn*32 + np*16 + brow_l;
                    uint32_t t0r,t1r,t2r,t3r;
                    LDSM_X4(t0r,t1r,t2r,t3r,
                            sbase + OFF_W1 + h*32768 + swz(nrow, bchk));
                    bh[np*2][0]=t0r; bh[np*2][1]=t1r; bh[np*2+1][0]=t2r; bh[np*2+1][1]=t3r;
                }
#pragma unroll
                for (int mt=0; mt<4; ++mt)
#pragma unroll
                    for (int nf=0; nf<4; ++nf)
                        MMA16816(c1[mt][nf], ah[mt], bh[nf]);
            }

            // epilogue1: +b1, relu -> H fp16
#pragma unroll
            for (int mt=0; mt<4; ++mt)
#pragma unroll
                for (int nf=0; nf<4; ++nf)
#pragma unroll
                    for (int i2=0; i2<2; ++i2){
                        int row = m0 + mt*16 + (lane>>2) + 8*i2;
                        int col = wn*32 + nf*8 + (lane&3)*2;
                        float v0 = fmaxf(c1[mt][nf][i2*2+0] + sB1[h*128 + col],     0.0f);
                        float v1 = fmaxf(c1[mt][nf][i2*2+1] + sB1[h*128 + col + 1], 0.0f);
                        *(uint32_t*)(smem + OFF_H + swz(row, col>>3) + (col&7)*2) = cvtH2(v0, v1);
                    }
            __syncthreads();

#pragma unroll 2
            for (int ks=0; ks<8; ++ks){
                uint32_t ah[4][4];
                int arow_l = lane & 15, achk = ks*2 + (lane >> 4);
#pragma unroll
                for (int mt=0; mt<4; ++mt){
                    int row = m0 + mt*16 + arow_l;
                    LDSM_X4(ah[mt][0],ah[mt][1],ah[mt][2],ah[mt][3],
                            sbase + OFF_H + swz(row, achk));
                }
                uint32_t bh[2][2];
                {
                    int nrow = wn*16 + (lane & 7) + ((lane >> 4) << 3);
                    int bchk = ks*2 + ((lane >> 3) & 1);
                    uint32_t t0r,t1r,t2r,t3r;
                    LDSM_X4(t0r,t1r,t2r,t3r,
                            sbase + OFF_W2 + h*16384 + swz(nrow, bchk));
                    bh[0][0]=t0r; bh[0][1]=t1r; bh[1][0]=t2r; bh[1][1]=t3r;
                }
#pragma unroll
                for (int mt=0; mt<4; ++mt)
#pragma unroll
                    for (int nf=0; nf<2; ++nf)
                        MMA16816(c2[mt][nf], ah[mt], bh[nf]);
            }
            __syncthreads();
        }

        // ---- scatter: m==1 -> direct STG.64; m>1 -> atomicAdd ----
#pragma unroll
        for (int mt=0; mt<4; ++mt)
#pragma unroll
            for (int nf=0; nf<2; ++nf)
#pragma unroll
                for (int r2=0; r2<2; ++r2){
                    int row = m0 + mt*16 + (lane>>2) + 8*r2;
                    int col = wn*16 + nf*8 + (lane&3)*2;
                    int tk  = sIdxC[row];
                    float w = ((t*BM + row) < Mv) ? g_invm[tk] : 0.0f;
                    float y0 = (c2[mt][nf][r2*2+0] + sB2[col])   * w;
                    float y1 = (c2[mt][nf][r2*2+1] + sB2[col+1]) * w;
                    float* dst = &out[(size_t)tk*ODIM + col];
                    if (w == 1.0f){
                        *reinterpret_cast<float2*>(dst) = make_float2(y0, y1);
                    } else if (w > 0.0f){
                        atomicAdd(dst,   y0);
                        atomicAdd(dst+1, y1);
                    }
                }

        curbuf ^= 1;
    }
}

// ---------------- launch ----------------
extern "C" void kernel_launch(void* const* d_in, const int* in_sizes, int n_in,
                              void* d_out, int out_size)
{
    const float* feat = (const float*)d_in[0];
    const float* Wg   = (const float*)d_in[1];
    const float* bg   = (const float*)d_in[2];
    const float* W1   = (const float*)d_in[3];
    const float* b1   = (const float*)d_in[4];
    const float* W2   = (const float*)d_in[5];
    const float* b2   = (const float*)d_in[6];
    float* out = (float*)d_out;

    int B = in_sizes[0] / FDIM;
    int Mv = (B + EXPERTS - 1) / EXPERTS;
    if (Mv < 1) Mv = 1;
    if (Mv > B) Mv = B;

    void* p_z;
    cudaGetSymbolAddress(&p_z, g_z);
    cudaMemsetAsync(p_z, 0, sizeof(ZeroBlk), 0);
    cudaMemsetAsync(d_out, 0, (size_t)out_size*sizeof(float), 0);

    int tb = 256;
    int gb = (B + tb - 1)/tb;
    k_cvtw<<<768, 256>>>(W1, W2);
    k_scores<<<gb, tb>>>(feat, Wg, bg, B);
    k_findbucket<<<EXPERTS, 1024>>>(Mv);
    k_hist2<<<dim3(gb, EXPERTS), tb>>>(B);
    k_findthresh2<<<EXPERTS, 1024>>>();
    k_select<<<dim3(gb, EXPERTS), tb>>>(B);
    k_resolve<<<EXPERTS, 256>>>();
    k_invm<<<gb, tb>>>(B);

    cudaFuncSetAttribute(k_mlp, cudaFuncAttributeMaxDynamicSharedMemorySize, SMEM_TOTAL);
    k_mlp<<<dim3(NCTA, EXPERTS), 256, SMEM_TOTAL>>>(feat, b1, b2, out, Mv);
}

// round 15
// speedup vs baseline: 2.5379x; 1.0824x over previous
#include <cuda_runtime.h>
#include <cuda_fp16.h>
#include <cstdint>

#define EXPERTS 16
#define FDIM 128
#define HDIM 256
#define ODIM 64
#define BMAX 262144
#define MMAX (BMAX/EXPERTS)
#define EQCAP 8192
#define BM 128
#define NCTA 9
#define NTHR 512

// ---------------- scratch ----------------
struct ZeroBlk {
    unsigned hist[EXPERTS * 65536];
    unsigned hist2[EXPERTS * 65536];
    unsigned selMask[BMAX];
    int      eqCnt[EXPERTS];
    int      idxCnt[EXPERTS];
};
__device__ ZeroBlk  g_z;
__device__ unsigned g_keys[(size_t)EXPERTS * BMAX];
__device__ unsigned g_b16[EXPERTS];
__device__ unsigned g_rankInB[EXPERTS];
__device__ unsigned g_T[EXPERTS];
__device__ unsigned g_needEq[EXPERTS];
__device__ int      g_eqList[EXPERTS * EQCAP];
__device__ int      g_idx[EXPERTS * MMAX];
__device__ float    g_invm[BMAX];
__device__ __half   g_w1h[(size_t)EXPERTS * HDIM * FDIM];
__device__ __half   g_w2h[(size_t)EXPERTS * ODIM * HDIM];
__device__ __half   g_feat16[(size_t)BMAX * FDIM];          // 64 MB fp16 features

// ---------------- helpers ----------------
__device__ __forceinline__ uint32_t smem_u32(const void* p) {
    uint32_t a;
    asm("{ .reg .u64 t; cvta.to.shared.u64 t, %1; cvt.u32.u64 %0, t; }" : "=r"(a) : "l"(p));
    return a;
}
#define LDSM_X4(r0,r1,r2,r3, addr) \
    asm volatile("ldmatrix.sync.aligned.m8n8.x4.shared.b16 {%0,%1,%2,%3}, [%4];" \
        : "=r"(r0),"=r"(r1),"=r"(r2),"=r"(r3) : "r"(addr))
#define MMA16816(d, a, b) \
    asm volatile("mma.sync.aligned.m16n8k16.row.col.f32.f16.f16.f32 " \
        "{%0,%1,%2,%3}, {%4,%5,%6,%7}, {%8,%9}, {%0,%1,%2,%3};" \
        : "+f"((d)[0]),"+f"((d)[1]),"+f"((d)[2]),"+f"((d)[3]) \
        : "r"((a)[0]),"r"((a)[1]),"r"((a)[2]),"r"((a)[3]), "r"((b)[0]),"r"((b)[1]))
#define CP_ASYNC16(dst, src) \
    asm volatile("cp.async.ca.shared.global [%0], [%1], 16;" :: "r"(dst), "l"(src) : "memory")
#define CP_COMMIT() asm volatile("cp.async.commit_group;" ::: "memory")
#define CP_WAIT(n)  asm volatile("cp.async.wait_group %0;" :: "n"(n) : "memory")

__device__ __forceinline__ unsigned cvtH2(float a, float b) {
    __half ha = __float2half(a), hb = __float2half(b);
    return (unsigned)__half_as_ushort(ha) | ((unsigned)__half_as_ushort(hb) << 16);
}
__device__ __forceinline__ unsigned swz(int row, int chunk) {
    return (unsigned)(row*256 + ((chunk ^ (row&7)) << 4));
}

// ---------------- K0a: weights -> fp16 ----------------
__global__ void k_cvtw(const float* __restrict__ W1, const float* __restrict__ W2)
{
    int i4 = (blockIdx.x*blockDim.x + threadIdx.x) * 4;
    const int n1 = EXPERTS*HDIM*FDIM;
    const int n2 = EXPERTS*ODIM*HDIM;
    if (i4 < n1){
        float4 v = *reinterpret_cast<const float4*>(W1 + i4);
        *reinterpret_cast<uint2*>(g_w1h + i4) = make_uint2(cvtH2(v.x,v.y), cvtH2(v.z,v.w));
    } else if (i4 - n1 < n2){
        int j4 = i4 - n1;
        float4 v = *reinterpret_cast<const float4*>(W2 + j4);
        *reinterpret_cast<uint2*>(g_w2h + j4) = make_uint2(cvtH2(v.x,v.y), cvtH2(v.z,v.w));
    }
}
// ---------------- K0b: features -> fp16 ----------------
__global__ void k_cvtf(const float* __restrict__ feat, int n)
{
    int i8 = (blockIdx.x*blockDim.x + threadIdx.x) * 8;
    if (i8 >= n) return;
    float4 a = *reinterpret_cast<const float4*>(feat + i8);
    float4 b = *reinterpret_cast<const float4*>(feat + i8 + 4);
    *reinterpret_cast<uint4*>(g_feat16 + i8) =
        make_uint4(cvtH2(a.x,a.y), cvtH2(a.z,a.w), cvtH2(b.x,b.y), cvtH2(b.z,b.w));
}

// ---------------- K1: gate scores (exact fp32) ----------------
__global__ void k_scores(const float* __restrict__ feat, const float* __restrict__ Wg,
                         const float* __restrict__ bg, int B)
{
    __shared__ float sW[EXPERTS*FDIM];
    __shared__ float sb[EXPERTS];
    for (int i = threadIdx.x; i < EXPERTS*FDIM; i += blockDim.x) sW[i] = Wg[i];
    if (threadIdx.x < EXPERTS) sb[threadIdx.x] = bg[threadIdx.x];
    __syncthreads();
    int b = blockIdx.x*blockDim.x + threadIdx.x;
    if (b >= B) return;
    const float4* row = reinterpret_cast<const float4*>(feat + (size_t)b*FDIM);
    float acc[EXPERTS];
#pragma unroll
    for (int e=0;e<EXPERTS;e++) acc[e] = sb[e];
#pragma unroll 4
    for (int j=0;j<FDIM/4;j++){
        float4 x = row[j];
#pragma unroll
        for (int e=0;e<EXPERTS;e++){
            float4 w = *reinterpret_cast<const float4*>(&sW[e*FDIM + j*4]);
            acc[e] += x.x*w.x + x.y*w.y + x.z*w.z + x.w*w.w;
        }
    }
#pragma unroll
    for (int e=0;e<EXPERTS;e++){
        unsigned u = __float_as_uint(acc[e]);
        u = (u & 0x80000000u) ? ~u : (u | 0x80000000u);
        g_keys[(size_t)e*B + b] = u;
        atomicAdd(&g_z.hist[e*65536 + (u>>16)], 1u);
    }
}

// ---------------- descending scan over 65536 bins ----------------
__device__ __forceinline__ void scan_find(const unsigned* __restrict__ hist, unsigned target,
                                          unsigned* out_bin, unsigned* out_rank)
{
    int t = threadIdx.x;
    const uint4* h4 = reinterpret_cast<const uint4*>(hist);
    int base4 = 16384 - 16*(t+1);
    unsigned s = 0;
#pragma unroll
    for (int i=0;i<16;i++){ uint4 v = h4[base4+i]; s += v.x+v.y+v.z+v.w; }
    __shared__ unsigned warpSum[32], warpPre[32];
    unsigned lane = t & 31, wid = t >> 5;
    unsigned inc = s;
#pragma unroll
    for (int o=1;o<32;o<<=1){ unsigned n = __shfl_up_sync(~0u, inc, o); if (lane >= o) inc += n; }
    if (lane == 31) warpSum[wid] = inc;
    __syncthreads();
    if (wid == 0){
        unsigned ws = warpSum[lane], winc = ws;
#pragma unroll
        for (int o=1;o<32;o<<=1){ unsigned n = __shfl_up_sync(~0u, winc, o); if (lane >= o) winc += n; }
        warpPre[lane] = winc - ws;
    }
    __syncthreads();
    unsigned before = warpPre[wid] + inc - s;
    unsigned after  = before + s;
    if (before < target && target <= after){
        unsigned acc = before;
        int hi = 65535 - 64*t;
        for (int b = hi; b > hi-64; --b){
            unsigned cnt = hist[b];
            if (acc + cnt >= target){ *out_bin = (unsigned)b; *out_rank = target - acc; break; }
            acc += cnt;
        }
    }
}

__global__ void k_findbucket(int Mv){
    int e = blockIdx.x;
    scan_find(g_z.hist + e*65536, (unsigned)Mv, &g_b16[e], &g_rankInB[e]);
}
__global__ void k_findthresh2(){
    int e = blockIdx.x;
    __shared__ unsigned sBin, sRank;
    if (threadIdx.x == 0){ sBin = 0xFFFFFFFFu; sRank = 0; }
    __syncthreads();
    scan_find(g_z.hist2 + e*65536, g_rankInB[e], &sBin, &sRank);
    __syncthreads();
    if (threadIdx.x == 0){
        g_T[e] = (g_b16[e] << 16) | sBin;
        g_needEq[e] = sRank;
    }
}

__global__ void k_hist2(int B){
    int e = blockIdx.y;
    int i = blockIdx.x*blockDim.x + threadIdx.x;
    if (i >= B) return;
    unsigned u = g_keys[(size_t)e*B + i];
    if ((u >> 16) == g_b16[e]) atomicAdd(&g_z.hist2[e*65536 + (u & 0xFFFFu)], 1u);
}

__global__ void k_select(int B){
    int e = blockIdx.y;
    int i = blockIdx.x*blockDim.x + threadIdx.x;
    int lane = threadIdx.x & 31;
    bool inb = (i < B);
    unsigned u = inb ? g_keys[(size_t)e*B + i] : 0u;
    unsigned t = g_T[e];
    bool gt = inb && (u > t);
    unsigned mask = __ballot_sync(~0u, gt);
    if (mask){
        int leader = __ffs(mask) - 1;
        int base = 0;
        if (lane == leader) base = atomicAdd(&g_z.idxCnt[e], __popc(mask));
        base = __shfl_sync(~0u, base, leader);
        if (gt){
            int p = base + __popc(mask & ((1u << lane) - 1u));
            g_idx[e*MMAX + p] = i;
            atomicOr(&g_z.selMask[i], 1u << e);
        }
    }
    if (inb && u == t){
        int p = atomicAdd(&g_z.eqCnt[e], 1);
        if (p < EQCAP) g_eqList[e*EQCAP + p] = i;
    }
}

__global__ void k_resolve(){
    int e = blockIdx.x;
    int n = g_z.eqCnt[e]; if (n > EQCAP) n = EQCAP;
    int need = (int)g_needEq[e];
    for (int j = threadIdx.x; j < n; j += blockDim.x){
        int v = g_eqList[e*EQCAP + j];
        int r = 0;
        for (int k=0;k<n;k++) r += (g_eqList[e*EQCAP + k] < v);
        if (r < need){
            int p = atomicAdd(&g_z.idxCnt[e], 1);
            g_idx[e*MMAX + p] = v;
            atomicOr(&g_z.selMask[v], 1u << e);
        }
    }
}

__global__ void k_invm(int B){
    int i = blockIdx.x*blockDim.x + threadIdx.x;
    if (i>=B) return;
    int c = __popc(g_z.selMask[i]);
    g_invm[i] = 1.0f / (float)(c > 0 ? c : 1);
}

// ---------------- K8: 512-thread persistent-expert fp16 mma MLP ----------------
#define HDR_IDXA  0
#define HDR_IDXB  512
#define HDR_B1    1024
#define HDR_B2    2048
#define POOL      2304
#define OFF_W1    (POOL + 0)        // 64KB
#define OFF_W2    (POOL + 65536)    // 32KB
#define OFF_XA    (POOL + 98304)    // 32KB
#define OFF_XB    (POOL + 131072)   // 32KB
#define OFF_H     (POOL + 163840)   // 32KB
#define SMEM_TOTAL (POOL + 196608)  // 198,912 bytes

__global__ __launch_bounds__(NTHR, 1)
void k_mlp(const float* __restrict__ b1, const float* __restrict__ b2,
           float* __restrict__ out, int Mv)
{
    extern __shared__ char smem[];
    uint32_t sbase = smem_u32(smem);
    int tid = threadIdx.x, lane = tid & 31, wid = tid >> 5;
    int e = blockIdx.y;
    int ntiles = (Mv + BM - 1) / BM;

    float* sB1 = (float*)(smem + HDR_B1);
    float* sB2 = (float*)(smem + HDR_B2);
    int* bufs[2] = { (int*)(smem + HDR_IDXA), (int*)(smem + HDR_IDXB) };
    uint32_t xoff[2] = { sbase + OFF_XA, sbase + OFF_XB };

    if (tid < HDIM) sB1[tid] = b1[e*HDIM + tid];
    if (tid < ODIM) sB2[tid] = b2[e*ODIM + tid];

    int t0 = blockIdx.x;
    if (t0 < ntiles && tid < BM){
        int slot = t0*BM + tid;
        bufs[0][tid] = (slot < Mv) ? g_idx[e*MMAX + slot] : 0;
    }
    __syncthreads();
    // gather first tile directly into XA (fp16, swizzled)
    if (t0 < ntiles){
        const int* sI = bufs[0];
#pragma unroll
        for (int it=0; it<4; ++it){
            int s = it*NTHR + tid, row = s >> 4, cg = s & 15;
            const __half* src = g_feat16 + (size_t)sI[row]*FDIM + cg*8;
            CP_ASYNC16(xoff[0] + swz(row, cg), src);
        }
    }
    CP_COMMIT();

    // resident fp16 weights
#pragma unroll
    for (int it=0; it<8; ++it){
        int s = it*NTHR + tid, row = s >> 4, cg = s & 15;
        uint4 v = *reinterpret_cast<const uint4*>(g_w1h + (size_t)(e*HDIM + row)*FDIM + cg*8);
        *(uint4*)(smem + OFF_W1 + (row>>7)*32768 + swz(row&127, cg)) = v;
    }
#pragma unroll
    for (int it=0; it<4; ++it){
        int s = it*NTHR + tid, row = s >> 5, cgg = s & 31;
        uint4 v = *reinterpret_cast<const uint4*>(g_w2h + (size_t)(e*ODIM + row)*HDIM + cgg*8);
        *(uint4*)(smem + OFF_W2 + (cgg>>4)*16384 + swz(row, cgg&15)) = v;
    }

    // 4m x 4n warp grid: each warp 32 rows; GEMM1 n-span 32, GEMM2 n-span 16
    int wm = wid & 3, wn = wid >> 2;
    int m0 = wm * 32;
    int curbuf = 0;

    for (int t = t0; t < ntiles; t += NCTA){
        int* sIdxC = bufs[curbuf];
        int* sIdxN = bufs[curbuf ^ 1];
        uint32_t xc = xoff[curbuf], xn = xoff[curbuf ^ 1];

        __syncthreads();                      // all warps done prev scatter; bufs/X reusable
        int tn = t + NCTA;
        if (tn < ntiles && tid < BM){
            int slot = tn*BM + tid;
            sIdxN[tid] = (slot < Mv) ? g_idx[e*MMAX + slot] : 0;
        }
        __syncthreads();                      // sIdxN visible

        if (tn < ntiles){
#pragma unroll
            for (int it=0; it<4; ++it){
                int s = it*NTHR + tid, row = s >> 4, cg = s & 15;
                const __half* src = g_feat16 + (size_t)sIdxN[row]*FDIM + cg*8;
                CP_ASYNC16(xn + swz(row, cg), src);
            }
        }
        CP_COMMIT();                           // groups: [g(t), g(t+NCTA)]
        CP_WAIT(1);                            // g(t) complete
        __syncthreads();                       // X[cur] visible to all warps

        float c2[2][2][4];
#pragma unroll
        for (int a=0;a<2;a++)
#pragma unroll
            for (int bb=0;bb<2;bb++)
#pragma unroll
                for (int i=0;i<4;i++) c2[a][bb][i] = 0.0f;

#pragma unroll 1
        for (int h=0; h<2; ++h){
            float c1[2][4][4];
#pragma unroll
            for (int a=0;a<2;a++)
#pragma unroll
                for (int bb=0;bb<4;bb++)
#pragma unroll
                    for (int i=0;i<4;i++) c1[a][bb][i] = 0.0f;

#pragma unroll 2
            for (int ks=0; ks<8; ++ks){
                uint32_t ah[2][4];
                int arow_l = lane & 15, achk = ks*2 + (lane >> 4);
#pragma unroll
                for (int mt=0; mt<2; ++mt){
                    int row = m0 + mt*16 + arow_l;
                    LDSM_X4(ah[mt][0],ah[mt][1],ah[mt][2],ah[mt][3], xc + swz(row, achk));
                }
                uint32_t bh[4][2];
                int brow_l = (lane & 7) + ((lane >> 4) << 3);
                int bchk = ks*2 + ((lane >> 3) & 1);
#pragma unroll
                for (int np=0; np<2; ++np){
                    int nrow = wn*32 + np*16 + brow_l;
                    uint32_t t0r,t1r,t2r,t3r;
                    LDSM_X4(t0r,t1r,t2r,t3r,
                            sbase + OFF_W1 + h*32768 + swz(nrow, bchk));
                    bh[np*2][0]=t0r; bh[np*2][1]=t1r; bh[np*2+1][0]=t2r; bh[np*2+1][1]=t3r;
                }
#pragma unroll
                for (int mt=0; mt<2; ++mt)
#pragma unroll
                    for (int nf=0; nf<4; ++nf)
                        MMA16816(c1[mt][nf], ah[mt], bh[nf]);
            }

            // epilogue1: +b1, relu -> H fp16
#pragma unroll
            for (int mt=0; mt<2; ++mt)
#pragma unroll
                for (int nf=0; nf<4; ++nf)
#pragma unroll
                    for (int i2=0; i2<2; ++i2){
                        int row = m0 + mt*16 + (lane>>2) + 8*i2;
                        int col = wn*32 + nf*8 + (lane&3)*2;
                        float v0 = fmaxf(c1[mt][nf][i2*2+0] + sB1[h*128 + col],     0.0f);
                        float v1 = fmaxf(c1[mt][nf][i2*2+1] + sB1[h*128 + col + 1], 0.0f);
                        *(uint32_t*)(smem + OFF_H + swz(row, col>>3) + (col&7)*2) = cvtH2(v0, v1);
                    }
            __syncthreads();                  // H ready

#pragma unroll 2
            for (int ks=0; ks<8; ++ks){
                uint32_t ah[2][4];
                int arow_l = lane & 15, achk = ks*2 + (lane >> 4);
#pragma unroll
                for (int mt=0; mt<2; ++mt){
                    int row = m0 + mt*16 + arow_l;
                    LDSM_X4(ah[mt][0],ah[mt][1],ah[mt][2],ah[mt][3],
                            sbase + OFF_H + swz(row, achk));
                }
                uint32_t bh[2][2];
                {
                    int nrow = wn*16 + (lane & 7) + ((lane >> 4) << 3);
                    int bchk = ks*2 + ((lane >> 3) & 1);
                    uint32_t t0r,t1r,t2r,t3r;
                    LDSM_X4(t0r,t1r,t2r,t3r,
                            sbase + OFF_W2 + h*16384 + swz(nrow, bchk));
                    bh[0][0]=t0r; bh[0][1]=t1r; bh[1][0]=t2r; bh[1][1]=t3r;
                }
#pragma unroll
                for (int mt=0; mt<2; ++mt)
#pragma unroll
                    for (int nf=0; nf<2; ++nf)
                        MMA16816(c2[mt][nf], ah[mt], bh[nf]);
            }
            __syncthreads();                  // H free for next half
        }

        // ---- scatter: m==1 -> direct STG.64; m>1 -> atomicAdd ----
#pragma unroll
        for (int mt=0; mt<2; ++mt)
#pragma unroll
            for (int nf=0; nf<2; ++nf)
#pragma unroll
                for (int r2=0; r2<2; ++r2){
                    int row = m0 + mt*16 + (lane>>2) + 8*r2;
                    int col = wn*16 + nf*8 + (lane&3)*2;
                    int tk  = sIdxC[row];
                    float w = ((t*BM + row) < Mv) ? g_invm[tk] : 0.0f;
                    float y0 = (c2[mt][nf][r2*2+0] + sB2[col])   * w;
                    float y1 = (c2[mt][nf][r2*2+1] + sB2[col+1]) * w;
                    float* dst = &out[(size_t)tk*ODIM + col];
                    if (w == 1.0f){
                        *reinterpret_cast<float2*>(dst) = make_float2(y0, y1);
                    } else if (w > 0.0f){
                        atomicAdd(dst,   y0);
                        atomicAdd(dst+1, y1);
                    }
                }

        curbuf ^= 1;
    }
}

// ---------------- launch ----------------
extern "C" void kernel_launch(void* const* d_in, const int* in_sizes, int n_in,
                              void* d_out, int out_size)
{
    const float* feat = (const float*)d_in[0];
    const float* Wg   = (const float*)d_in[1];
    const float* bg   = (const float*)d_in[2];
    const float* W1   = (const float*)d_in[3];
    const float* b1   = (const float*)d_in[4];
    const float* W2   = (const float*)d_in[5];
    const float* b2   = (const float*)d_in[6];
    float* out = (float*)d_out;

    int B = in_sizes[0] / FDIM;
    int Mv = (B + EXPERTS - 1) / EXPERTS;
    if (Mv < 1) Mv = 1;
    if (Mv > B) Mv = B;

    void* p_z;
    cudaGetSymbolAddress(&p_z, g_z);
    cudaMemsetAsync(p_z, 0, sizeof(ZeroBlk), 0);
    cudaMemsetAsync(d_out, 0, (size_t)out_size*sizeof(float), 0);

    int tb = 256;
    int gb = (B + tb - 1)/tb;
    k_cvtw<<<768, 256>>>(W1, W2);
    k_cvtf<<<(B*FDIM/8 + 255)/256, 256>>>(feat, B*FDIM);
    k_scores<<<gb, tb>>>(feat, Wg, bg, B);
    k_findbucket<<<EXPERTS, 1024>>>(Mv);
    k_hist2<<<dim3(gb, EXPERTS), tb>>>(B);
    k_findthresh2<<<EXPERTS, 1024>>>();
    k_select<<<dim3(gb, EXPERTS), tb>>>(B);
    k_resolve<<<EXPERTS, 256>>>();
    k_invm<<<gb, tb>>>(B);

    cudaFuncSetAttribute(k_mlp, cudaFuncAttributeMaxDynamicSharedMemorySize, SMEM_TOTAL);
    k_mlp<<<dim3(NCTA, EXPERTS), NTHR, SMEM_TOTAL>>>(b1, b2, out, Mv);
}